// round 13
// baseline (speedup 1.0000x reference)
#include <cuda_runtime.h>
#include <cuda_fp16.h>
#include <mma.h>
#include <math.h>
#include <cstdint>

using namespace nvcuda;

#define HH 128
#define WW 224
#define NN 4
#define HW (HH*WW)          // 28672
#define PTOT (NN*HW)        // 114688
#define NBLK2 (PTOT/224)    // 512 conv blocks (one image row each)
#define NBLKH (PTOT/128)    // 896 head blocks

// ---------------- scratch (__device__ globals, 16B aligned) -----------------
__device__ __align__(16) float  g_Y [(size_t)PTOT*288];
__device__ __align__(16) __half g_Xh[(size_t)PTOT*288];
__device__ __align__(16) __half g_Xl[(size_t)PTOT*288];
__device__ float  g_mean[288], g_rstd[288];
__device__ __align__(16) float2 g_part[(size_t)288*NBLK2];

// weights, layout [tap][k][n], single fp16
__device__ __align__(16) __half g_B1[9*256*288];
__device__ __align__(16) __half g_B2[9*288*192];
__device__ __align__(16) __half g_B3[9*192*192];
__device__ __align__(16) __half g_B4[9*192*192];
__device__ __align__(16) __half g_Bhd[9*96*16];

// ---------------- cp.async helpers ------------------------------------------
__device__ __forceinline__ void cp16(uint32_t s, const void* g, int sz) {
    asm volatile("cp.async.cg.shared.global [%0], [%1], 16, %2;"
                 :: "r"(s), "l"(g), "r"(sz));
}
#define CP_COMMIT() asm volatile("cp.async.commit_group;" ::: "memory")
#define CP_WAIT1()  asm volatile("cp.async.wait_group 1;" ::: "memory")

// ---------------- weight builders: [tap][k][n], fp16 ------------------------
__global__ void build_real(const float* __restrict__ wr,
                           const float* __restrict__ wi,
                           __half* __restrict__ B, int Cin, int Neff)
{
    int total = 9*Cin*Neff;
    int idx = blockIdx.x*256 + threadIdx.x;
    if (idx >= total) return;
    int n = idx % Neff; int rest = idx / Neff;
    int k = rest % Cin; int tap = rest / Cin;
    int co = n >> 1, part = n & 1;
    float v = (part ? wi : wr)[((size_t)co*Cin + k)*9 + tap];
    B[idx] = __float2half(v);
}

__global__ void build_cplx(const float* __restrict__ wr,
                           const float* __restrict__ wi,
                           __half* __restrict__ B, int Cin, int Neff)
{
    int Ktot = 2*Cin;
    int total = 9*Ktot*Neff;
    int idx = blockIdx.x*256 + threadIdx.x;
    if (idx >= total) return;
    int n = idx % Neff; int rest = idx / Neff;
    int k2 = rest % Ktot; int tap = rest / Ktot;
    int ci = k2 >> 1, cplx = k2 & 1;
    int co = n >> 1,  part = n & 1;
    float wrv = wr[((size_t)co*Cin + ci)*9 + tap];
    float wiv = wi[((size_t)co*Cin + ci)*9 + tap];
    float v = (part == 0) ? (cplx == 0 ?  wrv : -wiv)
                          : (cplx == 0 ?  wiv :  wrv);
    B[idx] = __float2half(v);
}

__global__ void build_head(const float* __restrict__ wc,
                           const float* __restrict__ wg,
                           __half* __restrict__ B)
{
    int total = 9*96*16;
    int idx = blockIdx.x*256 + threadIdx.x;
    if (idx >= total) return;
    int n = idx & 15; int rest = idx >> 4;
    int k = rest % 96; int tap = rest / 96;
    float v = 0.f;
    if (n == 0)      v = wc[(size_t)k*9 + tap];
    else if (n < 3)  v = wg[((size_t)(n-1)*96 + k)*9 + tap];
    B[idx] = __float2half(v);
}

// ---------------- input transpose: NCHW fp32 -> NHWC fp16 hi/lo (K=256) -----
__global__ void tr_in(const float* __restrict__ x,
                      __half* __restrict__ Xh, __half* __restrict__ Xl)
{
    __shared__ float sT[32][65];
    const int t = threadIdx.x;
    const int gp = blockIdx.x * 64;
    const int cb = blockIdx.y * 32;
    const int n = gp / HW, rbas = gp % HW;
#pragma unroll
    for (int it = 0; it < 8; ++it) {
        int idx = t + it*256;
        int cc = idx >> 6, pp = idx & 63;
        sT[cc][pp] = x[((size_t)(n*256 + cb + cc))*HW + rbas + pp];
    }
    __syncthreads();
#pragma unroll
    for (int it = 0; it < 8; ++it) {
        int idx = t + it*256;
        int cc = idx & 31, pp = idx >> 5;
        float v = sT[cc][pp];
        __half h = __float2half(v);
        size_t o = (size_t)(gp + pp)*256 + cb + cc;
        Xh[o] = h;
        Xl[o] = __float2half(v - __half2float(h));
    }
}

// ---------------- dh-chunked tap-GEMM conv ----------------------------------
// Block = one image row: M=224 (14 warps), N = NFRAG*16. Chunk = (dh, k0):
// A tile (226 slots x 32 k, hi/lo) shared across the 3 dw taps via shifted
// wmma views; B holds 3 dw slices. 2-pass fp16 split: D = ah*bh + al*bh.
template<int NFRAG, bool STATS>
__global__ __launch_bounds__(448, 1)
void conv_dh(const __half* __restrict__ Xh,
             const __half* __restrict__ Xl,
             const __half* __restrict__ Bg,
             float* __restrict__ Y, float2* __restrict__ part,
             int K, int Neff)
{
    constexpr int NCOLS = NFRAG*16;
    constexpr int NSEG  = NCOLS/8;               // 16B segs per B row
    constexpr int BSTR  = NCOLS + 8;             // halfs
    constexpr int AHALF = 226*80;                // 18080 B (one half)
    constexpr int OBB   = 2*AHALF;               // 36160
    constexpr int STAGE = OBB + 3*32*BSTR*2;
    extern __shared__ char smc[];
    const uint32_t sb = (uint32_t)__cvta_generic_to_shared(smc);

    const int t    = threadIdx.x;
    const int wid  = t >> 5;
    const int tbase= blockIdx.x * 224;           // aligned to image row
    const int h0   = (tbase / 224) % 128;
    const int nb   = blockIdx.y * NCOLS;
    const int kch  = K >> 5;
    const int CC   = 3 * kch;

    wmma::fragment<wmma::accumulator,16,16,16,float> acc[NFRAG];
#pragma unroll
    for (int f = 0; f < NFRAG; ++f) wmma::fill_fragment(acc[f], 0.f);

    auto LOAD = [&](int cc, int buf) {
        const uint32_t st = sb + buf*STAGE;
        int dhi = cc / kch;                      // 0..2
        int k0  = (cc - dhi*kch) << 5;
        int dh  = dhi - 1;
        bool rowok = ((unsigned)(h0 + dh) < 128u);
        // A: 226 slots x 4 segs x 2 halves = 1808 tasks
#pragma unroll
        for (int it = 0; it < 5; ++it) {
            int task = t + it*448;
            if (task < 1808) {
                int half = task >= 904;
                int t2 = half ? task - 904 : task;
                int j = t2 >> 2, seg = t2 & 3;
                bool ok = rowok && (j != 0) && (j != 225);
                size_t off = ok ? ((size_t)(tbase + dh*224 + j - 1)*K + k0 + seg*8) : 0;
                cp16(st + half*AHALF + j*80 + seg*16,
                     (half ? Xl : Xh) + off, ok ? 16 : 0);
            }
        }
        // B: 3 dw x 32 rows x NSEG segs
        const int BT = 3*32*NSEG;
#pragma unroll
        for (int it = 0; it < (BT + 447)/448; ++it) {
            int task = t + it*448;
            if (task < BT) {
                int dwi = task / (32*NSEG);
                int tk  = task - dwi*(32*NSEG);
                int row = tk / NSEG, seg = tk - row*NSEG;
                int tap = dhi*3 + dwi;
                size_t off = ((size_t)tap*K + k0 + row)*Neff + nb + seg*8;
                cp16(st + OBB + dwi*(32*BSTR*2) + row*(BSTR*2) + seg*16,
                     Bg + off, 16);
            }
        }
        CP_COMMIT();
    };

    LOAD(0, 0);
    for (int cc = 0; cc < CC; ++cc) {
        const int cur = cc & 1;
        if (cc + 1 < CC) LOAD(cc+1, cur^1);
        else CP_COMMIT();                        // keep wait_group accounting
        CP_WAIT1();
        __syncthreads();
        const __half* Ah = (const __half*)(smc + cur*STAGE);
        const __half* Al = (const __half*)(smc + cur*STAGE + AHALF);
        const __half* Bb = (const __half*)(smc + cur*STAGE + OBB);
#pragma unroll
        for (int dwi = 0; dwi < 3; ++dwi) {
            const __half* Bdw = Bb + dwi*32*BSTR;
#pragma unroll
            for (int ks = 0; ks < 2; ++ks) {
                wmma::fragment<wmma::matrix_a,16,16,16,__half,wmma::row_major> ah, al;
                // output pixel p -> A slot (p - tbase) + 1 + dw = row + dwi
                wmma::load_matrix_sync(ah, Ah + (wid*16 + dwi)*40 + ks*16, 40);
                wmma::load_matrix_sync(al, Al + (wid*16 + dwi)*40 + ks*16, 40);
#pragma unroll
                for (int f = 0; f < NFRAG; ++f) {
                    wmma::fragment<wmma::matrix_b,16,16,16,__half,wmma::row_major> bh;
                    wmma::load_matrix_sync(bh, Bdw + ks*16*BSTR + f*16, BSTR);
                    wmma::mma_sync(acc[f], ah, bh, acc[f]);
                    wmma::mma_sync(acc[f], al, bh, acc[f]);
                }
            }
        }
        __syncthreads();
    }

    // epilogue: per-fragment wave through smem; coalesced Y writes + stats
    float*  sD = (float*)smc;                    // 14 warps x 16x20 = 17920 B
    float2* sP = (float2*)(smc + 17920);         // [28 grp][16 col]
#pragma unroll
    for (int g = 0; g < NFRAG; ++g) {
        wmma::store_matrix_sync(sD + wid*320, acc[g], 20, wmma::mem_row_major);
        __syncthreads();
#pragma unroll
        for (int it = 0; it < 2; ++it) {
            int task = t + it*448;               // 224 rows x 4 segs
            int row = task >> 2, s4 = task & 3;
            float4 v = *(const float4*)(sD + (row>>4)*320 + (row&15)*20 + s4*4);
            *(float4*)(Y + (size_t)(tbase+row)*Neff + nb + g*16 + s4*4) = v;
        }
        if (STATS) {
            int col = t & 15, grp = t >> 4;      // grp 0..27
            float s = 0.f, q = 0.f;
#pragma unroll
            for (int r8 = 0; r8 < 8; ++r8) {
                int row = grp*8 + r8;
                float v = sD[(row>>4)*320 + (row&15)*20 + col];
                s += v; q = fmaf(v, v, q);
            }
            sP[grp*16 + col] = make_float2(s, q);
        }
        __syncthreads();
        if (STATS && t < 16) {
            float s = 0.f, q = 0.f;
#pragma unroll
            for (int gg = 0; gg < 28; ++gg) {
                float2 v = sP[gg*16 + t];
                s += v.x; q += v.y;
            }
            part[(size_t)(nb + g*16 + t)*NBLK2 + blockIdx.x] = make_float2(s, q);
        }
        __syncthreads();
    }
}

// ---------------- head conv (128-pixel tap-GEMM, NFRAG=1) --------------------
__global__ __launch_bounds__(256, 1)
void conv_head_tc(const __half* __restrict__ Xh,
                  const __half* __restrict__ Xl,
                  const __half* __restrict__ Bg,
                  float* __restrict__ Y, int K, int Neff)
{
    constexpr int BSTR  = 24;                    // 16+8 halfs
    constexpr int OB    = 20480;
    constexpr int STAGE = OB + 32*BSTR*2;        // 22016
    extern __shared__ char smc[];
    const uint32_t sb = (uint32_t)__cvta_generic_to_shared(smc);

    const int t   = threadIdx.x;
    const int wid = t >> 5;
    const int tb  = blockIdx.x * 128;
    const int rb  = tb % HW;
    const int kch = K >> 5;
    const int CC  = 9 * kch;

    wmma::fragment<wmma::accumulator,16,16,16,float> acc;
    wmma::fill_fragment(acc, 0.f);

    auto LOAD = [&](int cc, int buf) {
        const uint32_t st = sb + buf*STAGE;
        int tap = cc / kch;
        int k0  = (cc - tap*kch) << 5;
        int dh = tap/3 - 1, dw = tap - (tap/3)*3 - 1;
#pragma unroll
        for (int it = 0; it < 4; ++it) {
            int task = t + it*256;
            int half = task >> 9;
            int t2   = task & 511;
            int row = t2 >> 2, seg = t2 & 3;
            int r = rb + row;
            int hh = r / 224;
            int ww = r - hh*224;
            bool ok = ((unsigned)(hh+dh) < 128u) && ((unsigned)(ww+dw) < 224u);
            size_t off = ok ? ((size_t)(tb + row + dh*224 + dw)*K + k0 + seg*8) : 0;
            cp16(st + half*10240 + row*80 + seg*16, (half ? Xl : Xh) + off, ok ? 16 : 0);
        }
        if (t < 32*2) {   // 32 rows x 2 segs
            int row = t >> 1, seg = t & 1;
            size_t off = ((size_t)tap*K + k0 + row)*Neff + seg*8;
            cp16(st + OB + row*(BSTR*2) + seg*16, Bg + off, 16);
        }
        CP_COMMIT();
    };

    LOAD(0, 0);
    for (int cc = 0; cc < CC; ++cc) {
        const int cur = cc & 1;
        if (cc + 1 < CC) LOAD(cc+1, cur^1);
        else CP_COMMIT();
        CP_WAIT1();
        __syncthreads();
        const __half* Ah = (const __half*)(smc + cur*STAGE);
        const __half* Al = (const __half*)(smc + cur*STAGE + 10240);
        const __half* Bh = (const __half*)(smc + cur*STAGE + OB);
#pragma unroll
        for (int ks = 0; ks < 2; ++ks) {
            wmma::fragment<wmma::matrix_a,16,16,16,__half,wmma::row_major> ah, al;
            wmma::load_matrix_sync(ah, Ah + wid*16*40 + ks*16, 40);
            wmma::load_matrix_sync(al, Al + wid*16*40 + ks*16, 40);
            wmma::fragment<wmma::matrix_b,16,16,16,__half,wmma::row_major> bh;
            wmma::load_matrix_sync(bh, Bh + ks*16*BSTR, BSTR);
            wmma::mma_sync(acc, ah, bh, acc);
            wmma::mma_sync(acc, al, bh, acc);
        }
        __syncthreads();
    }

    float* sD = (float*)smc;
    wmma::store_matrix_sync(sD + wid*320, acc, 20, wmma::mem_row_major);
    __syncthreads();
#pragma unroll
    for (int it = 0; it < 2; ++it) {
        int task = t + it*256;
        int row = task >> 2, s4 = task & 3;
        float4 v = *(const float4*)(sD + (row>>4)*320 + (row&15)*20 + s4*4);
        *(float4*)(Y + (size_t)(tb+row)*16 + s4*4) = v;
    }
}

// ---------------- BN stats stage 2: NBLK2 partials -> mean/rstd -------------
__global__ void bn_stats2(const float2* __restrict__ part,
                          float* __restrict__ mean, float* __restrict__ rstd)
{
    const int c = blockIdx.x, t = threadIdx.x;
    double s = 0.0, q = 0.0;
    for (int i = t; i < NBLK2; i += 256) {
        float2 v = part[(size_t)c*NBLK2 + i];
        s += (double)v.x; q += (double)v.y;
    }
    __shared__ double ss[256], sq[256];
    ss[t] = s; sq[t] = q;
    __syncthreads();
    for (int o = 128; o > 0; o >>= 1) {
        if (t < o) { ss[t] += ss[t+o]; sq[t] += sq[t+o]; }
        __syncthreads();
    }
    if (t == 0) {
        double cnt = (double)PTOT;
        double m = ss[0] / cnt;
        double var = sq[0] / cnt - m*m;
        mean[c] = (float)m;
        rstd[c] = (float)(1.0 / sqrt(var + 1e-5));
    }
}

// -------- BN apply + ReLU + fp16 hi/lo split, channel-paired -----------------
__global__ void bn_apply(const float* __restrict__ Y, int C2,
                         const float* __restrict__ mean,
                         const float* __restrict__ rstd,
                         const float* __restrict__ g, const float* __restrict__ b,
                         __half* __restrict__ Xh, __half* __restrict__ Xl)
{
    const int c = threadIdx.x * 2;               // C2/2 threads
    const int pb = blockIdx.x * 256;
    const float gc = g[c>>1], bc = b[c>>1];
    const float sc0 = rstd[c]*gc,   bi0 = bc - mean[c]*sc0;
    const float sc1 = rstd[c+1]*gc, bi1 = bc - mean[c+1]*sc1;
    for (int p = 0; p < 256; ++p) {
        size_t o = (size_t)(pb+p)*C2 + c;
        float2 y = *(const float2*)(Y + o);
        float v0 = fmaxf(fmaf(y.x, sc0, bi0), 0.f);
        float v1 = fmaxf(fmaf(y.y, sc1, bi1), 0.f);
        __half2 h = __floats2half2_rn(v0, v1);
        *(__half2*)(Xh + o) = h;
        float2 hf = __half22float2(h);
        *(__half2*)(Xl + o) = __floats2half2_rn(v0 - hf.x, v1 - hf.y);
    }
}

// -------- layer-4: BN + ReLU + |z| -> NHWC fp16 hi/lo M [P,96] ---------------
__global__ void bn_mag(const float* __restrict__ Y,
                       const float* __restrict__ mean,
                       const float* __restrict__ rstd,
                       const float* __restrict__ g, const float* __restrict__ b,
                       __half* __restrict__ Mh, __half* __restrict__ Ml)
{
    const int c = threadIdx.x;                   // 96
    const int pb = blockIdx.x * 256;
    const float scr = rstd[2*c]*g[c];
    const float bir = b[c] - mean[2*c]*scr;
    const float sci = rstd[2*c+1]*g[c];
    const float bii = b[c] - mean[2*c+1]*sci;
    for (int p = 0; p < 256; ++p) {
        const float* yp = Y + (size_t)(pb+p)*192 + 2*c;
        float a = fmaxf(fmaf(yp[0], scr, bir), 0.f);
        float d = fmaxf(fmaf(yp[1], sci, bii), 0.f);
        float m = sqrtf(a*a + d*d);
        __half h = __float2half(m);
        size_t o = (size_t)(pb+p)*96 + c;
        Mh[o] = h;
        Ml[o] = __float2half(m - __half2float(h));
    }
}

// -------- head finish: bias + sigmoid(ch0) + NCHW transpose ------------------
__global__ void head_fin(const float* __restrict__ Yh,
                         const float* __restrict__ bc,
                         const float* __restrict__ bg,
                         float* __restrict__ out)
{
    int p = blockIdx.x*256 + threadIdx.x;
    float y0 = Yh[(size_t)p*16 + 0] + bc[0];
    float y1 = Yh[(size_t)p*16 + 1] + bg[0];
    float y2 = Yh[(size_t)p*16 + 2] + bg[1];
    y0 = 1.f / (1.f + expf(-y0));
    int n = p / HW, hw = p - n*HW;
    out[((size_t)(n*3 + 0))*HW + hw] = y0;
    out[((size_t)(n*3 + 1))*HW + hw] = y1;
    out[((size_t)(n*3 + 2))*HW + hw] = y2;
}

// ---------------- driver -----------------------------------------------------
extern "C" void kernel_launch(void* const* d_in, const int* in_sizes, int n_in,
                              void* d_out, int out_size)
{
    (void)in_sizes; (void)n_in; (void)out_size;
    const float* x   = (const float*)d_in[0];
    const float* w1r = (const float*)d_in[1];
    const float* w1i = (const float*)d_in[2];
    const float* g1  = (const float*)d_in[3];
    const float* b1  = (const float*)d_in[4];
    const float* w2r = (const float*)d_in[5];
    const float* w2i = (const float*)d_in[6];
    const float* g2  = (const float*)d_in[7];
    const float* b2  = (const float*)d_in[8];
    const float* w3r = (const float*)d_in[9];
    const float* w3i = (const float*)d_in[10];
    const float* g3  = (const float*)d_in[11];
    const float* b3  = (const float*)d_in[12];
    const float* w4r = (const float*)d_in[13];
    const float* w4i = (const float*)d_in[14];
    const float* g4  = (const float*)d_in[15];
    const float* b4  = (const float*)d_in[16];
    const float* wc  = (const float*)d_in[17];
    const float* bc  = (const float*)d_in[18];
    const float* wg  = (const float*)d_in[19];
    const float* bg  = (const float*)d_in[20];
    float* out = (float*)d_out;

    float *Y, *mean, *rstd;
    float2* part;
    __half *Xh, *Xl, *B1, *B2, *B3, *B4, *Bhd;
    cudaGetSymbolAddress((void**)&Y,   g_Y);
    cudaGetSymbolAddress((void**)&mean,g_mean);
    cudaGetSymbolAddress((void**)&rstd,g_rstd);
    cudaGetSymbolAddress((void**)&part,g_part);
    cudaGetSymbolAddress((void**)&Xh,  g_Xh);
    cudaGetSymbolAddress((void**)&Xl,  g_Xl);
    cudaGetSymbolAddress((void**)&B1,  g_B1);
    cudaGetSymbolAddress((void**)&B2,  g_B2);
    cudaGetSymbolAddress((void**)&B3,  g_B3);
    cudaGetSymbolAddress((void**)&B4,  g_B4);
    cudaGetSymbolAddress((void**)&Bhd, g_Bhd);

    // conv_dh<6>: STAGE = 36160 + 3*32*104*2 = 56128; dyn smem = 112256
    cudaFuncSetAttribute((const void*)conv_dh<6,true>,
                         cudaFuncAttributeMaxDynamicSharedMemorySize, 112256);
    cudaFuncSetAttribute((const void*)conv_head_tc,
                         cudaFuncAttributeMaxDynamicSharedMemorySize, 44032);

    // weights ([tap][k][n], fp16) + input layout
    build_real<<<(9*256*288 + 255)/256, 256>>>(w1r, w1i, B1, 256, 288);
    build_cplx<<<(9*288*192 + 255)/256, 256>>>(w2r, w2i, B2, 144, 192);
    build_cplx<<<(9*192*192 + 255)/256, 256>>>(w3r, w3i, B3, 96, 192);
    build_cplx<<<(9*192*192 + 255)/256, 256>>>(w4r, w4i, B4, 96, 192);
    build_head<<<(9*96*16 + 255)/256, 256>>>(wc, wg, Bhd);
    tr_in<<<dim3(PTOT/64, 8), 256>>>(x, Xh, Xl);

    // Layer 1: K=256 real, Neff=288 (3 y-blocks of 96)
    conv_dh<6,true><<<dim3(NBLK2, 3), 448, 112256>>>(Xh, Xl, B1, Y, part, 256, 288);
    bn_stats2<<<288, 256>>>(part, mean, rstd);
    bn_apply<<<448, 144>>>(Y, 288, mean, rstd, g1, b1, Xh, Xl);

    // Layer 2: K=288, Neff=192 (2 y-blocks of 96)
    conv_dh<6,true><<<dim3(NBLK2, 2), 448, 112256>>>(Xh, Xl, B2, Y, part, 288, 192);
    bn_stats2<<<192, 256>>>(part, mean, rstd);
    bn_apply<<<448, 96>>>(Y, 192, mean, rstd, g2, b2, Xh, Xl);

    // Layer 3: K=192, Neff=192
    conv_dh<6,true><<<dim3(NBLK2, 2), 448, 112256>>>(Xh, Xl, B3, Y, part, 192, 192);
    bn_stats2<<<192, 256>>>(part, mean, rstd);
    bn_apply<<<448, 96>>>(Y, 192, mean, rstd, g3, b3, Xh, Xl);

    // Layer 4: K=192, Neff=192, then BN+ReLU+|z| -> NHWC fp16 M (reuse Xh/Xl)
    conv_dh<6,true><<<dim3(NBLK2, 2), 448, 112256>>>(Xh, Xl, B4, Y, part, 192, 192);
    bn_stats2<<<192, 256>>>(part, mean, rstd);
    bn_mag<<<448, 96>>>(Y, mean, rstd, g4, b4, Xh, Xl);

    // head: tensor-path conv (K=96, 16 cols, 3 used) -> Y stride 16, then finish
    conv_head_tc<<<NBLKH, 256, 44032>>>(Xh, Xl, Bhd, Y, 96, 16);
    head_fin<<<PTOT/256, 256>>>(Y, bc, bg, out);
}

// round 14
// speedup vs baseline: 1.0799x; 1.0799x over previous
#include <cuda_runtime.h>
#include <cuda_fp16.h>
#include <mma.h>
#include <math.h>
#include <cstdint>

using namespace nvcuda;

#define HH 128
#define WW 224
#define NN 4
#define HW (HH*WW)          // 28672
#define PTOT (NN*HW)        // 114688
#define NBLK3 (PTOT/112)    // 1024 conv blocks (half image row each)
#define NBLKH (PTOT/128)    // 896 head blocks

// ---------------- scratch (__device__ globals, 16B aligned) -----------------
__device__ __align__(16) float  g_Y [(size_t)PTOT*288];
__device__ __align__(16) __half g_Xh[(size_t)PTOT*288];
__device__ __align__(16) __half g_Xl[(size_t)PTOT*288];
__device__ float  g_mean[288], g_rstd[288];
__device__ __align__(16) float2 g_part[(size_t)288*NBLK3];

// weights, layout [tap][k][n], single fp16
__device__ __align__(16) __half g_B1[9*256*288];
__device__ __align__(16) __half g_B2[9*288*192];
__device__ __align__(16) __half g_B3[9*192*192];
__device__ __align__(16) __half g_B4[9*192*192];
__device__ __align__(16) __half g_Bhd[9*96*16];

// ---------------- cp.async helpers ------------------------------------------
__device__ __forceinline__ void cp16(uint32_t s, const void* g, int sz) {
    asm volatile("cp.async.cg.shared.global [%0], [%1], 16, %2;"
                 :: "r"(s), "l"(g), "r"(sz));
}
#define CP_COMMIT() asm volatile("cp.async.commit_group;" ::: "memory")
#define CP_WAIT1()  asm volatile("cp.async.wait_group 1;" ::: "memory")

// ---------------- weight builders: [tap][k][n], fp16 ------------------------
__global__ void build_real(const float* __restrict__ wr,
                           const float* __restrict__ wi,
                           __half* __restrict__ B, int Cin, int Neff)
{
    int total = 9*Cin*Neff;
    int idx = blockIdx.x*256 + threadIdx.x;
    if (idx >= total) return;
    int n = idx % Neff; int rest = idx / Neff;
    int k = rest % Cin; int tap = rest / Cin;
    int co = n >> 1, part = n & 1;
    float v = (part ? wi : wr)[((size_t)co*Cin + k)*9 + tap];
    B[idx] = __float2half(v);
}

__global__ void build_cplx(const float* __restrict__ wr,
                           const float* __restrict__ wi,
                           __half* __restrict__ B, int Cin, int Neff)
{
    int Ktot = 2*Cin;
    int total = 9*Ktot*Neff;
    int idx = blockIdx.x*256 + threadIdx.x;
    if (idx >= total) return;
    int n = idx % Neff; int rest = idx / Neff;
    int k2 = rest % Ktot; int tap = rest / Ktot;
    int ci = k2 >> 1, cplx = k2 & 1;
    int co = n >> 1,  part = n & 1;
    float wrv = wr[((size_t)co*Cin + ci)*9 + tap];
    float wiv = wi[((size_t)co*Cin + ci)*9 + tap];
    float v = (part == 0) ? (cplx == 0 ?  wrv : -wiv)
                          : (cplx == 0 ?  wiv :  wrv);
    B[idx] = __float2half(v);
}

__global__ void build_head(const float* __restrict__ wc,
                           const float* __restrict__ wg,
                           __half* __restrict__ B)
{
    int total = 9*96*16;
    int idx = blockIdx.x*256 + threadIdx.x;
    if (idx >= total) return;
    int n = idx & 15; int rest = idx >> 4;
    int k = rest % 96; int tap = rest / 96;
    float v = 0.f;
    if (n == 0)      v = wc[(size_t)k*9 + tap];
    else if (n < 3)  v = wg[((size_t)(n-1)*96 + k)*9 + tap];
    B[idx] = __float2half(v);
}

// ---------------- input transpose: NCHW fp32 -> NHWC fp16 hi/lo (K=256) -----
__global__ void tr_in(const float* __restrict__ x,
                      __half* __restrict__ Xh, __half* __restrict__ Xl)
{
    __shared__ float sT[32][65];
    const int t = threadIdx.x;
    const int gp = blockIdx.x * 64;
    const int cb = blockIdx.y * 32;
    const int n = gp / HW, rbas = gp % HW;
#pragma unroll
    for (int it = 0; it < 8; ++it) {
        int idx = t + it*256;
        int cc = idx >> 6, pp = idx & 63;
        sT[cc][pp] = x[((size_t)(n*256 + cb + cc))*HW + rbas + pp];
    }
    __syncthreads();
#pragma unroll
    for (int it = 0; it < 8; ++it) {
        int idx = t + it*256;
        int cc = idx & 31, pp = idx >> 5;
        float v = sT[cc][pp];
        __half h = __float2half(v);
        size_t o = (size_t)(gp + pp)*256 + cb + cc;
        Xh[o] = h;
        Xl[o] = __float2half(v - __half2float(h));
    }
}

// ---------------- dh-chunked tap-GEMM conv, half-row blocks ------------------
// Block = half image row: M=112 (7 warps, 224 thr), N = NFRAG*16.
// Chunk = (dh, k0): A tile (114 slots x 32 k, hi/lo) shared across the 3 dw
// taps via shifted wmma views; B holds 3 dw slices.
// 2-pass fp16 split: D = ah*bh + al*bh.
template<int NFRAG, bool STATS>
__global__ __launch_bounds__(224, 2)
void conv_dh(const __half* __restrict__ Xh,
             const __half* __restrict__ Xl,
             const __half* __restrict__ Bg,
             float* __restrict__ Y, float2* __restrict__ part,
             int K, int Neff)
{
    constexpr int NCOLS = NFRAG*16;
    constexpr int NSEG  = NCOLS/8;               // 16B segs per B row
    constexpr int BSTR  = NCOLS + 8;             // halfs
    constexpr int AHALF = 114*80;                // 9120 B (one half)
    constexpr int OBB   = 2*AHALF;               // 18240
    constexpr int STAGE = OBB + 3*32*BSTR*2;
    extern __shared__ char smc[];
    const uint32_t sb = (uint32_t)__cvta_generic_to_shared(smc);

    const int t    = threadIdx.x;
    const int wid  = t >> 5;                     // 0..6
    const int tbase= blockIdx.x * 112;
    const int wb   = tbase % 224;                // 0 or 112
    const int h0   = (tbase % HW) / 224;
    const int nb   = blockIdx.y * NCOLS;
    const int kch  = K >> 5;
    const int CC   = 3 * kch;

    wmma::fragment<wmma::accumulator,16,16,16,float> acc[NFRAG];
#pragma unroll
    for (int f = 0; f < NFRAG; ++f) wmma::fill_fragment(acc[f], 0.f);

    auto LOAD = [&](int cc, int buf) {
        const uint32_t st = sb + buf*STAGE;
        int dhi = cc / kch;                      // 0..2
        int k0  = (cc - dhi*kch) << 5;
        int dh  = dhi - 1;
        bool rowok = ((unsigned)(h0 + dh) < 128u);
        // A: 114 slots x 4 segs x 2 halves = 912 tasks
#pragma unroll
        for (int it = 0; it < 5; ++it) {
            int task = t + it*224;
            if (task < 912) {
                int half = task >= 456;
                int t2 = half ? task - 456 : task;
                int j = t2 >> 2, seg = t2 & 3;
                int wcoord = wb + j - 1;
                bool ok = rowok && ((unsigned)wcoord < 224u);
                size_t off = ok ? ((size_t)(tbase + dh*224 + j - 1)*K + k0 + seg*8) : 0;
                cp16(st + half*AHALF + j*80 + seg*16,
                     (half ? Xl : Xh) + off, ok ? 16 : 0);
            }
        }
        // B: 3 dw x 32 rows x NSEG segs
        const int BT = 3*32*NSEG;
#pragma unroll
        for (int it = 0; it < (BT + 223)/224; ++it) {
            int task = t + it*224;
            if (task < BT) {
                int dwi = task / (32*NSEG);
                int tk  = task - dwi*(32*NSEG);
                int row = tk / NSEG, seg = tk - row*NSEG;
                int tap = dhi*3 + dwi;
                size_t off = ((size_t)tap*K + k0 + row)*Neff + nb + seg*8;
                cp16(st + OBB + dwi*(32*BSTR*2) + row*(BSTR*2) + seg*16,
                     Bg + off, 16);
            }
        }
        CP_COMMIT();
    };

    LOAD(0, 0);
    for (int cc = 0; cc < CC; ++cc) {
        const int cur = cc & 1;
        if (cc + 1 < CC) LOAD(cc+1, cur^1);
        else CP_COMMIT();                        // keep wait_group accounting
        CP_WAIT1();
        __syncthreads();
        const __half* Ah = (const __half*)(smc + cur*STAGE);
        const __half* Al = (const __half*)(smc + cur*STAGE + AHALF);
        const __half* Bb = (const __half*)(smc + cur*STAGE + OBB);
#pragma unroll
        for (int dwi = 0; dwi < 3; ++dwi) {
            const __half* Bdw = Bb + dwi*32*BSTR;
#pragma unroll
            for (int ks = 0; ks < 2; ++ks) {
                wmma::fragment<wmma::matrix_a,16,16,16,__half,wmma::row_major> ah, al;
                // output pixel row r -> A slot r + dwi
                wmma::load_matrix_sync(ah, Ah + (wid*16 + dwi)*40 + ks*16, 40);
                wmma::load_matrix_sync(al, Al + (wid*16 + dwi)*40 + ks*16, 40);
#pragma unroll
                for (int f = 0; f < NFRAG; ++f) {
                    wmma::fragment<wmma::matrix_b,16,16,16,__half,wmma::row_major> bh;
                    wmma::load_matrix_sync(bh, Bdw + ks*16*BSTR + f*16, BSTR);
                    wmma::mma_sync(acc[f], ah, bh, acc[f]);
                    wmma::mma_sync(acc[f], al, bh, acc[f]);
                }
            }
        }
        __syncthreads();
    }

    // epilogue: per-fragment wave through smem; coalesced Y writes + stats
    float*  sD = (float*)smc;                    // 7 warps x 16x20 = 8960 B
    float2* sP = (float2*)(smc + 8960);          // [14 grp][16 col]
#pragma unroll
    for (int g = 0; g < NFRAG; ++g) {
        wmma::store_matrix_sync(sD + wid*320, acc[g], 20, wmma::mem_row_major);
        __syncthreads();
#pragma unroll
        for (int it = 0; it < 2; ++it) {
            int task = t + it*224;               // 112 rows x 4 segs
            int row = task >> 2, s4 = task & 3;
            float4 v = *(const float4*)(sD + (row>>4)*320 + (row&15)*20 + s4*4);
            *(float4*)(Y + (size_t)(tbase+row)*Neff + nb + g*16 + s4*4) = v;
        }
        if (STATS) {
            int col = t & 15, grp = t >> 4;      // grp 0..13
            float s = 0.f, q = 0.f;
#pragma unroll
            for (int r8 = 0; r8 < 8; ++r8) {
                int row = grp*8 + r8;
                float v = sD[(row>>4)*320 + (row&15)*20 + col];
                s += v; q = fmaf(v, v, q);
            }
            sP[grp*16 + col] = make_float2(s, q);
        }
        __syncthreads();
        if (STATS && t < 16) {
            float s = 0.f, q = 0.f;
#pragma unroll
            for (int gg = 0; gg < 14; ++gg) {
                float2 v = sP[gg*16 + t];
                s += v.x; q += v.y;
            }
            part[(size_t)(nb + g*16 + t)*NBLK3 + blockIdx.x] = make_float2(s, q);
        }
        __syncthreads();
    }
}

// ---------------- head conv (128-pixel tap-GEMM, NFRAG=1) --------------------
__global__ __launch_bounds__(256, 1)
void conv_head_tc(const __half* __restrict__ Xh,
                  const __half* __restrict__ Xl,
                  const __half* __restrict__ Bg,
                  float* __restrict__ Y, int K, int Neff)
{
    constexpr int BSTR  = 24;                    // 16+8 halfs
    constexpr int OB    = 20480;
    constexpr int STAGE = OB + 32*BSTR*2;        // 22016
    extern __shared__ char smc[];
    const uint32_t sb = (uint32_t)__cvta_generic_to_shared(smc);

    const int t   = threadIdx.x;
    const int wid = t >> 5;
    const int tb  = blockIdx.x * 128;
    const int rb  = tb % HW;
    const int kch = K >> 5;
    const int CC  = 9 * kch;

    wmma::fragment<wmma::accumulator,16,16,16,float> acc;
    wmma::fill_fragment(acc, 0.f);

    auto LOAD = [&](int cc, int buf) {
        const uint32_t st = sb + buf*STAGE;
        int tap = cc / kch;
        int k0  = (cc - tap*kch) << 5;
        int dh = tap/3 - 1, dw = tap - (tap/3)*3 - 1;
#pragma unroll
        for (int it = 0; it < 4; ++it) {
            int task = t + it*256;
            int half = task >> 9;
            int t2   = task & 511;
            int row = t2 >> 2, seg = t2 & 3;
            int r = rb + row;
            int hh = r / 224;
            int ww = r - hh*224;
            bool ok = ((unsigned)(hh+dh) < 128u) && ((unsigned)(ww+dw) < 224u);
            size_t off = ok ? ((size_t)(tb + row + dh*224 + dw)*K + k0 + seg*8) : 0;
            cp16(st + half*10240 + row*80 + seg*16, (half ? Xl : Xh) + off, ok ? 16 : 0);
        }
        if (t < 32*2) {   // 32 rows x 2 segs
            int row = t >> 1, seg = t & 1;
            size_t off = ((size_t)tap*K + k0 + row)*Neff + seg*8;
            cp16(st + OB + row*(BSTR*2) + seg*16, Bg + off, 16);
        }
        CP_COMMIT();
    };

    LOAD(0, 0);
    for (int cc = 0; cc < CC; ++cc) {
        const int cur = cc & 1;
        if (cc + 1 < CC) LOAD(cc+1, cur^1);
        else CP_COMMIT();
        CP_WAIT1();
        __syncthreads();
        const __half* Ah = (const __half*)(smc + cur*STAGE);
        const __half* Al = (const __half*)(smc + cur*STAGE + 10240);
        const __half* Bh = (const __half*)(smc + cur*STAGE + OB);
#pragma unroll
        for (int ks = 0; ks < 2; ++ks) {
            wmma::fragment<wmma::matrix_a,16,16,16,__half,wmma::row_major> ah, al;
            wmma::load_matrix_sync(ah, Ah + wid*16*40 + ks*16, 40);
            wmma::load_matrix_sync(al, Al + wid*16*40 + ks*16, 40);
            wmma::fragment<wmma::matrix_b,16,16,16,__half,wmma::row_major> bh;
            wmma::load_matrix_sync(bh, Bh + ks*16*BSTR, BSTR);
            wmma::mma_sync(acc, ah, bh, acc);
            wmma::mma_sync(acc, al, bh, acc);
        }
        __syncthreads();
    }

    float* sD = (float*)smc;
    wmma::store_matrix_sync(sD + wid*320, acc, 20, wmma::mem_row_major);
    __syncthreads();
#pragma unroll
    for (int it = 0; it < 2; ++it) {
        int task = t + it*256;
        int row = task >> 2, s4 = task & 3;
        float4 v = *(const float4*)(sD + (row>>4)*320 + (row&15)*20 + s4*4);
        *(float4*)(Y + (size_t)(tb+row)*16 + s4*4) = v;
    }
}

// ---------------- BN stats stage 2: NBLK3 partials -> mean/rstd -------------
__global__ void bn_stats2(const float2* __restrict__ part,
                          float* __restrict__ mean, float* __restrict__ rstd)
{
    const int c = blockIdx.x, t = threadIdx.x;
    double s = 0.0, q = 0.0;
    for (int i = t; i < NBLK3; i += 256) {
        float2 v = part[(size_t)c*NBLK3 + i];
        s += (double)v.x; q += (double)v.y;
    }
    __shared__ double ss[256], sq[256];
    ss[t] = s; sq[t] = q;
    __syncthreads();
    for (int o = 128; o > 0; o >>= 1) {
        if (t < o) { ss[t] += ss[t+o]; sq[t] += sq[t+o]; }
        __syncthreads();
    }
    if (t == 0) {
        double cnt = (double)PTOT;
        double m = ss[0] / cnt;
        double var = sq[0] / cnt - m*m;
        mean[c] = (float)m;
        rstd[c] = (float)(1.0 / sqrt(var + 1e-5));
    }
}

// -------- BN apply + ReLU + fp16 hi/lo split, channel-paired -----------------
__global__ void bn_apply(const float* __restrict__ Y, int C2,
                         const float* __restrict__ mean,
                         const float* __restrict__ rstd,
                         const float* __restrict__ g, const float* __restrict__ b,
                         __half* __restrict__ Xh, __half* __restrict__ Xl)
{
    const int c = threadIdx.x * 2;               // C2/2 threads
    const int pb = blockIdx.x * 256;
    const float gc = g[c>>1], bc = b[c>>1];
    const float sc0 = rstd[c]*gc,   bi0 = bc - mean[c]*sc0;
    const float sc1 = rstd[c+1]*gc, bi1 = bc - mean[c+1]*sc1;
    for (int p = 0; p < 256; ++p) {
        size_t o = (size_t)(pb+p)*C2 + c;
        float2 y = *(const float2*)(Y + o);
        float v0 = fmaxf(fmaf(y.x, sc0, bi0), 0.f);
        float v1 = fmaxf(fmaf(y.y, sc1, bi1), 0.f);
        __half2 h = __floats2half2_rn(v0, v1);
        *(__half2*)(Xh + o) = h;
        float2 hf = __half22float2(h);
        *(__half2*)(Xl + o) = __floats2half2_rn(v0 - hf.x, v1 - hf.y);
    }
}

// -------- layer-4: BN + ReLU + |z| -> NHWC fp16 hi/lo M [P,96] ---------------
__global__ void bn_mag(const float* __restrict__ Y,
                       const float* __restrict__ mean,
                       const float* __restrict__ rstd,
                       const float* __restrict__ g, const float* __restrict__ b,
                       __half* __restrict__ Mh, __half* __restrict__ Ml)
{
    const int c = threadIdx.x;                   // 96
    const int pb = blockIdx.x * 256;
    const float scr = rstd[2*c]*g[c];
    const float bir = b[c] - mean[2*c]*scr;
    const float sci = rstd[2*c+1]*g[c];
    const float bii = b[c] - mean[2*c+1]*sci;
    for (int p = 0; p < 256; ++p) {
        const float* yp = Y + (size_t)(pb+p)*192 + 2*c;
        float a = fmaxf(fmaf(yp[0], scr, bir), 0.f);
        float d = fmaxf(fmaf(yp[1], sci, bii), 0.f);
        float m = sqrtf(a*a + d*d);
        __half h = __float2half(m);
        size_t o = (size_t)(pb+p)*96 + c;
        Mh[o] = h;
        Ml[o] = __float2half(m - __half2float(h));
    }
}

// -------- head finish: bias + sigmoid(ch0) + NCHW transpose ------------------
__global__ void head_fin(const float* __restrict__ Yh,
                         const float* __restrict__ bc,
                         const float* __restrict__ bg,
                         float* __restrict__ out)
{
    int p = blockIdx.x*256 + threadIdx.x;
    float y0 = Yh[(size_t)p*16 + 0] + bc[0];
    float y1 = Yh[(size_t)p*16 + 1] + bg[0];
    float y2 = Yh[(size_t)p*16 + 2] + bg[1];
    y0 = 1.f / (1.f + expf(-y0));
    int n = p / HW, hw = p - n*HW;
    out[((size_t)(n*3 + 0))*HW + hw] = y0;
    out[((size_t)(n*3 + 1))*HW + hw] = y1;
    out[((size_t)(n*3 + 2))*HW + hw] = y2;
}

// ---------------- driver -----------------------------------------------------
extern "C" void kernel_launch(void* const* d_in, const int* in_sizes, int n_in,
                              void* d_out, int out_size)
{
    (void)in_sizes; (void)n_in; (void)out_size;
    const float* x   = (const float*)d_in[0];
    const float* w1r = (const float*)d_in[1];
    const float* w1i = (const float*)d_in[2];
    const float* g1  = (const float*)d_in[3];
    const float* b1  = (const float*)d_in[4];
    const float* w2r = (const float*)d_in[5];
    const float* w2i = (const float*)d_in[6];
    const float* g2  = (const float*)d_in[7];
    const float* b2  = (const float*)d_in[8];
    const float* w3r = (const float*)d_in[9];
    const float* w3i = (const float*)d_in[10];
    const float* g3  = (const float*)d_in[11];
    const float* b3  = (const float*)d_in[12];
    const float* w4r = (const float*)d_in[13];
    const float* w4i = (const float*)d_in[14];
    const float* g4  = (const float*)d_in[15];
    const float* b4  = (const float*)d_in[16];
    const float* wc  = (const float*)d_in[17];
    const float* bc  = (const float*)d_in[18];
    const float* wg  = (const float*)d_in[19];
    const float* bg  = (const float*)d_in[20];
    float* out = (float*)d_out;

    float *Y, *mean, *rstd;
    float2* part;
    __half *Xh, *Xl, *B1, *B2, *B3, *B4, *Bhd;
    cudaGetSymbolAddress((void**)&Y,   g_Y);
    cudaGetSymbolAddress((void**)&mean,g_mean);
    cudaGetSymbolAddress((void**)&rstd,g_rstd);
    cudaGetSymbolAddress((void**)&part,g_part);
    cudaGetSymbolAddress((void**)&Xh,  g_Xh);
    cudaGetSymbolAddress((void**)&Xl,  g_Xl);
    cudaGetSymbolAddress((void**)&B1,  g_B1);
    cudaGetSymbolAddress((void**)&B2,  g_B2);
    cudaGetSymbolAddress((void**)&B3,  g_B3);
    cudaGetSymbolAddress((void**)&B4,  g_B4);
    cudaGetSymbolAddress((void**)&Bhd, g_Bhd);

    // conv_dh<12>: STAGE = 18240 + 3*32*200*2 = 56640; dyn smem = 113280
    // conv_dh<9> : STAGE = 18240 + 3*32*152*2 = 47424; dyn smem =  94848
    cudaFuncSetAttribute((const void*)conv_dh<12,true>,
                         cudaFuncAttributeMaxDynamicSharedMemorySize, 113280);
    cudaFuncSetAttribute((const void*)conv_dh<9,true>,
                         cudaFuncAttributeMaxDynamicSharedMemorySize, 94848);
    cudaFuncSetAttribute((const void*)conv_head_tc,
                         cudaFuncAttributeMaxDynamicSharedMemorySize, 44032);

    // weights ([tap][k][n], fp16) + input layout
    build_real<<<(9*256*288 + 255)/256, 256>>>(w1r, w1i, B1, 256, 288);
    build_cplx<<<(9*288*192 + 255)/256, 256>>>(w2r, w2i, B2, 144, 192);
    build_cplx<<<(9*192*192 + 255)/256, 256>>>(w3r, w3i, B3, 96, 192);
    build_cplx<<<(9*192*192 + 255)/256, 256>>>(w4r, w4i, B4, 96, 192);
    build_head<<<(9*96*16 + 255)/256, 256>>>(wc, wg, Bhd);
    tr_in<<<dim3(PTOT/64, 8), 256>>>(x, Xh, Xl);

    // Layer 1: K=256 real, Neff=288 (2 y-blocks of 144)
    conv_dh<9,true><<<dim3(NBLK3, 2), 224, 94848>>>(Xh, Xl, B1, Y, part, 256, 288);
    bn_stats2<<<288, 256>>>(part, mean, rstd);
    bn_apply<<<448, 144>>>(Y, 288, mean, rstd, g1, b1, Xh, Xl);

    // Layer 2: K=288, Neff=192
    conv_dh<12,true><<<dim3(NBLK3, 1), 224, 113280>>>(Xh, Xl, B2, Y, part, 288, 192);
    bn_stats2<<<192, 256>>>(part, mean, rstd);
    bn_apply<<<448, 96>>>(Y, 192, mean, rstd, g2, b2, Xh, Xl);

    // Layer 3: K=192, Neff=192
    conv_dh<12,true><<<dim3(NBLK3, 1), 224, 113280>>>(Xh, Xl, B3, Y, part, 192, 192);
    bn_stats2<<<192, 256>>>(part, mean, rstd);
    bn_apply<<<448, 96>>>(Y, 192, mean, rstd, g3, b3, Xh, Xl);

    // Layer 4: K=192, Neff=192, then BN+ReLU+|z| -> NHWC fp16 M (reuse Xh/Xl)
    conv_dh<12,true><<<dim3(NBLK3, 1), 224, 113280>>>(Xh, Xl, B4, Y, part, 192, 192);
    bn_stats2<<<192, 256>>>(part, mean, rstd);
    bn_mag<<<448, 96>>>(Y, mean, rstd, g4, b4, Xh, Xl);

    // head: tensor-path conv (K=96, 16 cols, 3 used) -> Y stride 16, then finish
    conv_head_tc<<<NBLKH, 256, 44032>>>(Xh, Xl, Bhd, Y, 96, 16);
    head_fin<<<PTOT/256, 256>>>(Y, bc, bg, out);
}

// round 15
// speedup vs baseline: 1.1126x; 1.0303x over previous
#include <cuda_runtime.h>
#include <cuda_fp16.h>
#include <mma.h>
#include <math.h>
#include <cstdint>

using namespace nvcuda;

#define HH 128
#define WW 224
#define NN 4
#define HW (HH*WW)          // 28672
#define PTOT (NN*HW)        // 114688
#define NBLK3 (PTOT/112)    // 1024 conv blocks (half image row each)

// ---------------- scratch (__device__ globals, 16B aligned) -----------------
__device__ __align__(16) float  g_Y [(size_t)PTOT*288];
__device__ __align__(16) __half g_Xh[(size_t)PTOT*288];
__device__ __align__(16) __half g_Xl[(size_t)PTOT*288];
__device__ float  g_mean[288], g_rstd[288];
__device__ __align__(16) float2 g_part[(size_t)288*NBLK3];

// weights, layout [tap][k][n], single fp16
#define S_B1 (9*256*288)
#define S_B2 (9*288*192)
#define S_B3 (9*192*192)
#define S_B4 (9*192*192)
#define S_BH (9*96*16)
__device__ __align__(16) __half g_B1[S_B1];
__device__ __align__(16) __half g_B2[S_B2];
__device__ __align__(16) __half g_B3[S_B3];
__device__ __align__(16) __half g_B4[S_B4];
__device__ __align__(16) __half g_Bhd[S_BH];

// ---------------- cp.async helpers ------------------------------------------
__device__ __forceinline__ void cp16(uint32_t s, const void* g, int sz) {
    asm volatile("cp.async.cg.shared.global [%0], [%1], 16, %2;"
                 :: "r"(s), "l"(g), "r"(sz));
}
#define CP_COMMIT() asm volatile("cp.async.commit_group;" ::: "memory")
#define CP_WAIT1()  asm volatile("cp.async.wait_group 1;" ::: "memory")

// ---------------- merged weight builder --------------------------------------
__device__ __forceinline__ float w_real(const float* wr, const float* wi,
                                        int Cin, int Neff, int idx) {
    int n = idx % Neff; int rest = idx / Neff;
    int k = rest % Cin; int tap = rest / Cin;
    int co = n >> 1, part = n & 1;
    return (part ? wi : wr)[((size_t)co*Cin + k)*9 + tap];
}
__device__ __forceinline__ float w_cplx(const float* wr, const float* wi,
                                        int Cin, int Neff, int idx) {
    int Ktot = 2*Cin;
    int n = idx % Neff; int rest = idx / Neff;
    int k2 = rest % Ktot; int tap = rest / Ktot;
    int ci = k2 >> 1, cplx = k2 & 1;
    int co = n >> 1,  part = n & 1;
    float wrv = wr[((size_t)co*Cin + ci)*9 + tap];
    float wiv = wi[((size_t)co*Cin + ci)*9 + tap];
    return (part == 0) ? (cplx == 0 ?  wrv : -wiv)
                       : (cplx == 0 ?  wiv :  wrv);
}

__global__ void build_all(const float* __restrict__ w1r, const float* __restrict__ w1i,
                          const float* __restrict__ w2r, const float* __restrict__ w2i,
                          const float* __restrict__ w3r, const float* __restrict__ w3i,
                          const float* __restrict__ w4r, const float* __restrict__ w4i,
                          const float* __restrict__ wc,  const float* __restrict__ wg,
                          __half* __restrict__ B1, __half* __restrict__ B2,
                          __half* __restrict__ B3, __half* __restrict__ B4,
                          __half* __restrict__ Bhd)
{
    int idx = blockIdx.x*256 + threadIdx.x;
    if (idx < S_B1) {
        B1[idx] = __float2half(w_real(w1r, w1i, 256, 288, idx));
        return;
    }
    idx -= S_B1;
    if (idx < S_B2) {
        B2[idx] = __float2half(w_cplx(w2r, w2i, 144, 192, idx));
        return;
    }
    idx -= S_B2;
    if (idx < S_B3) {
        B3[idx] = __float2half(w_cplx(w3r, w3i, 96, 192, idx));
        return;
    }
    idx -= S_B3;
    if (idx < S_B4) {
        B4[idx] = __float2half(w_cplx(w4r, w4i, 96, 192, idx));
        return;
    }
    idx -= S_B4;
    if (idx < S_BH) {
        int n = idx & 15; int rest = idx >> 4;
        int k = rest % 96; int tap = rest / 96;
        float v = 0.f;
        if (n == 0)      v = wc[(size_t)k*9 + tap];
        else if (n < 3)  v = wg[((size_t)(n-1)*96 + k)*9 + tap];
        Bhd[idx] = __float2half(v);
    }
}

// ---------------- input transpose: NCHW fp32 -> NHWC fp16 hi/lo (K=256) -----
__global__ void tr_in(const float* __restrict__ x,
                      __half* __restrict__ Xh, __half* __restrict__ Xl)
{
    __shared__ float sT[32][65];
    const int t = threadIdx.x;
    const int gp = blockIdx.x * 64;
    const int cb = blockIdx.y * 32;
    const int n = gp / HW, rbas = gp % HW;
#pragma unroll
    for (int it = 0; it < 8; ++it) {
        int idx = t + it*256;
        int cc = idx >> 6, pp = idx & 63;
        sT[cc][pp] = x[((size_t)(n*256 + cb + cc))*HW + rbas + pp];
    }
    __syncthreads();
#pragma unroll
    for (int it = 0; it < 8; ++it) {
        int idx = t + it*256;
        int cc = idx & 31, pp = idx >> 5;
        float v = sT[cc][pp];
        __half h = __float2half(v);
        size_t o = (size_t)(gp + pp)*256 + cb + cc;
        Xh[o] = h;
        Xl[o] = __float2half(v - __half2float(h));
    }
}

// ---------------- dh-chunked tap-GEMM conv, half-row blocks ------------------
// Block = half image row: M=112 (7 warps, 224 thr), N = NFRAG*16.
// Chunk = (dh, k0): A tile (114 slots x 32 k, hi/lo) shared across the 3 dw
// taps via shifted wmma views; B holds 3 dw slices.
// 2-pass fp16 split: D = ah*bh + al*bh.
template<int NFRAG, bool STATS>
__global__ __launch_bounds__(224, 2)
void conv_dh(const __half* __restrict__ Xh,
             const __half* __restrict__ Xl,
             const __half* __restrict__ Bg,
             float* __restrict__ Y, float2* __restrict__ part,
             int K, int Neff)
{
    constexpr int NCOLS = NFRAG*16;
    constexpr int NSEG  = NCOLS/8;               // 16B segs per B row
    constexpr int BSTR  = NCOLS + 8;             // halfs
    constexpr int AHALF = 114*80;                // 9120 B (one half)
    constexpr int OBB   = 2*AHALF;               // 18240
    constexpr int STAGE = OBB + 3*32*BSTR*2;
    extern __shared__ char smc[];
    const uint32_t sb = (uint32_t)__cvta_generic_to_shared(smc);

    const int t    = threadIdx.x;
    const int wid  = t >> 5;                     // 0..6
    const int tbase= blockIdx.x * 112;
    const int wb   = tbase % 224;                // 0 or 112
    const int h0   = (tbase % HW) / 224;
    const int nb   = blockIdx.y * NCOLS;
    const int kch  = K >> 5;
    const int CC   = 3 * kch;

    wmma::fragment<wmma::accumulator,16,16,16,float> acc[NFRAG];
#pragma unroll
    for (int f = 0; f < NFRAG; ++f) wmma::fill_fragment(acc[f], 0.f);

    auto LOAD = [&](int cc, int buf) {
        const uint32_t st = sb + buf*STAGE;
        int dhi = cc / kch;                      // 0..2
        int k0  = (cc - dhi*kch) << 5;
        int dh  = dhi - 1;
        bool rowok = ((unsigned)(h0 + dh) < 128u);
        // A: 114 slots x 4 segs x 2 halves = 912 tasks
#pragma unroll
        for (int it = 0; it < 5; ++it) {
            int task = t + it*224;
            if (task < 912) {
                int half = task >= 456;
                int t2 = half ? task - 456 : task;
                int j = t2 >> 2, seg = t2 & 3;
                int wcoord = wb + j - 1;
                bool ok = rowok && ((unsigned)wcoord < 224u);
                size_t off = ok ? ((size_t)(tbase + dh*224 + j - 1)*K + k0 + seg*8) : 0;
                cp16(st + half*AHALF + j*80 + seg*16,
                     (half ? Xl : Xh) + off, ok ? 16 : 0);
            }
        }
        // B: 3 dw x 32 rows x NSEG segs
        const int BT = 3*32*NSEG;
#pragma unroll
        for (int it = 0; it < (BT + 223)/224; ++it) {
            int task = t + it*224;
            if (task < BT) {
                int dwi = task / (32*NSEG);
                int tk  = task - dwi*(32*NSEG);
                int row = tk / NSEG, seg = tk - row*NSEG;
                int tap = dhi*3 + dwi;
                size_t off = ((size_t)tap*K + k0 + row)*Neff + nb + seg*8;
                cp16(st + OBB + dwi*(32*BSTR*2) + row*(BSTR*2) + seg*16,
                     Bg + off, 16);
            }
        }
        CP_COMMIT();
    };

    LOAD(0, 0);
    for (int cc = 0; cc < CC; ++cc) {
        const int cur = cc & 1;
        if (cc + 1 < CC) LOAD(cc+1, cur^1);
        else CP_COMMIT();                        // keep wait_group accounting
        CP_WAIT1();
        __syncthreads();
        const __half* Ah = (const __half*)(smc + cur*STAGE);
        const __half* Al = (const __half*)(smc + cur*STAGE + AHALF);
        const __half* Bb = (const __half*)(smc + cur*STAGE + OBB);
#pragma unroll
        for (int dwi = 0; dwi < 3; ++dwi) {
            const __half* Bdw = Bb + dwi*32*BSTR;
#pragma unroll
            for (int ks = 0; ks < 2; ++ks) {
                wmma::fragment<wmma::matrix_a,16,16,16,__half,wmma::row_major> ah, al;
                // output pixel row r -> A slot r + dwi
                wmma::load_matrix_sync(ah, Ah + (wid*16 + dwi)*40 + ks*16, 40);
                wmma::load_matrix_sync(al, Al + (wid*16 + dwi)*40 + ks*16, 40);
#pragma unroll
                for (int f = 0; f < NFRAG; ++f) {
                    wmma::fragment<wmma::matrix_b,16,16,16,__half,wmma::row_major> bh;
                    wmma::load_matrix_sync(bh, Bdw + ks*16*BSTR + f*16, BSTR);
                    wmma::mma_sync(acc[f], ah, bh, acc[f]);
                    wmma::mma_sync(acc[f], al, bh, acc[f]);
                }
            }
        }
        __syncthreads();
    }

    // epilogue: per-fragment wave through smem; coalesced Y writes + stats
    float*  sD = (float*)smc;                    // 7 warps x 16x20 = 8960 B
    float2* sP = (float2*)(smc + 8960);          // [14 grp][16 col]
#pragma unroll
    for (int g = 0; g < NFRAG; ++g) {
        wmma::store_matrix_sync(sD + wid*320, acc[g], 20, wmma::mem_row_major);
        __syncthreads();
#pragma unroll
        for (int it = 0; it < 2; ++it) {
            int task = t + it*224;               // 112 rows x 4 segs
            int row = task >> 2, s4 = task & 3;
            float4 v = *(const float4*)(sD + (row>>4)*320 + (row&15)*20 + s4*4);
            *(float4*)(Y + (size_t)(tbase+row)*Neff + nb + g*16 + s4*4) = v;
        }
        if (STATS) {
            int col = t & 15, grp = t >> 4;      // grp 0..13
            float s = 0.f, q = 0.f;
#pragma unroll
            for (int r8 = 0; r8 < 8; ++r8) {
                int row = grp*8 + r8;
                float v = sD[(row>>4)*320 + (row&15)*20 + col];
                s += v; q = fmaf(v, v, q);
            }
            sP[grp*16 + col] = make_float2(s, q);
        }
        __syncthreads();
        if (STATS && t < 16) {
            float s = 0.f, q = 0.f;
#pragma unroll
            for (int gg = 0; gg < 14; ++gg) {
                float2 v = sP[gg*16 + t];
                s += v.x; q += v.y;
            }
            part[(size_t)(nb + g*16 + t)*NBLK3 + blockIdx.x] = make_float2(s, q);
        }
        __syncthreads();
    }
}

// ---------------- BN stats stage 2: NBLK3 partials -> mean/rstd -------------
__global__ void bn_stats2(const float2* __restrict__ part,
                          float* __restrict__ mean, float* __restrict__ rstd)
{
    const int c = blockIdx.x, t = threadIdx.x;
    double s = 0.0, q = 0.0;
    for (int i = t; i < NBLK3; i += 256) {
        float2 v = part[(size_t)c*NBLK3 + i];
        s += (double)v.x; q += (double)v.y;
    }
    __shared__ double ss[256], sq[256];
    ss[t] = s; sq[t] = q;
    __syncthreads();
    for (int o = 128; o > 0; o >>= 1) {
        if (t < o) { ss[t] += ss[t+o]; sq[t] += sq[t+o]; }
        __syncthreads();
    }
    if (t == 0) {
        double cnt = (double)PTOT;
        double m = ss[0] / cnt;
        double var = sq[0] / cnt - m*m;
        mean[c] = (float)m;
        rstd[c] = (float)(1.0 / sqrt(var + 1e-5));
    }
}

// -------- BN apply + ReLU + fp16 hi/lo split, flat grid ----------------------
__global__ void bn_apply(const float* __restrict__ Y, int C2,
                         const float* __restrict__ mean,
                         const float* __restrict__ rstd,
                         const float* __restrict__ g, const float* __restrict__ b,
                         __half* __restrict__ Xh, __half* __restrict__ Xl)
{
    int idx = blockIdx.x*256 + threadIdx.x;      // one channel-pair per thread
    int half = C2 >> 1;
    int p = idx / half, cp = idx - p*half;
    int c = cp*2;
    const float gc = g[c>>1], bc = b[c>>1];
    const float sc0 = rstd[c]*gc,   bi0 = bc - mean[c]*sc0;
    const float sc1 = rstd[c+1]*gc, bi1 = bc - mean[c+1]*sc1;
    size_t o = (size_t)p*C2 + c;
    float2 y = *(const float2*)(Y + o);
    float v0 = fmaxf(fmaf(y.x, sc0, bi0), 0.f);
    float v1 = fmaxf(fmaf(y.y, sc1, bi1), 0.f);
    __half2 h = __floats2half2_rn(v0, v1);
    *(__half2*)(Xh + o) = h;
    float2 hf = __half22float2(h);
    *(__half2*)(Xl + o) = __floats2half2_rn(v0 - hf.x, v1 - hf.y);
}

// -------- layer-4: BN + ReLU + |z| -> NHWC fp16 hi/lo M [P,96] ---------------
__global__ void bn_mag(const float* __restrict__ Y,
                       const float* __restrict__ mean,
                       const float* __restrict__ rstd,
                       const float* __restrict__ g, const float* __restrict__ b,
                       __half* __restrict__ Mh, __half* __restrict__ Ml)
{
    const int c = threadIdx.x;                   // 96
    const int pb = blockIdx.x * 256;
    const float scr = rstd[2*c]*g[c];
    const float bir = b[c] - mean[2*c]*scr;
    const float sci = rstd[2*c+1]*g[c];
    const float bii = b[c] - mean[2*c+1]*sci;
    for (int p = 0; p < 256; ++p) {
        const float* yp = Y + (size_t)(pb+p)*192 + 2*c;
        float a = fmaxf(fmaf(yp[0], scr, bir), 0.f);
        float d = fmaxf(fmaf(yp[1], sci, bii), 0.f);
        float m = sqrtf(a*a + d*d);
        __half h = __float2half(m);
        size_t o = (size_t)(pb+p)*96 + c;
        Mh[o] = h;
        Ml[o] = __float2half(m - __half2float(h));
    }
}

// -------- head finish: bias + sigmoid(ch0) + NCHW transpose ------------------
__global__ void head_fin(const float* __restrict__ Yh,
                         const float* __restrict__ bc,
                         const float* __restrict__ bg,
                         float* __restrict__ out)
{
    int p = blockIdx.x*256 + threadIdx.x;
    float y0 = Yh[(size_t)p*16 + 0] + bc[0];
    float y1 = Yh[(size_t)p*16 + 1] + bg[0];
    float y2 = Yh[(size_t)p*16 + 2] + bg[1];
    y0 = 1.f / (1.f + expf(-y0));
    int n = p / HW, hw = p - n*HW;
    out[((size_t)(n*3 + 0))*HW + hw] = y0;
    out[((size_t)(n*3 + 1))*HW + hw] = y1;
    out[((size_t)(n*3 + 2))*HW + hw] = y2;
}

// ---------------- driver -----------------------------------------------------
extern "C" void kernel_launch(void* const* d_in, const int* in_sizes, int n_in,
                              void* d_out, int out_size)
{
    (void)in_sizes; (void)n_in; (void)out_size;
    const float* x   = (const float*)d_in[0];
    const float* w1r = (const float*)d_in[1];
    const float* w1i = (const float*)d_in[2];
    const float* g1  = (const float*)d_in[3];
    const float* b1  = (const float*)d_in[4];
    const float* w2r = (const float*)d_in[5];
    const float* w2i = (const float*)d_in[6];
    const float* g2  = (const float*)d_in[7];
    const float* b2  = (const float*)d_in[8];
    const float* w3r = (const float*)d_in[9];
    const float* w3i = (const float*)d_in[10];
    const float* g3  = (const float*)d_in[11];
    const float* b3  = (const float*)d_in[12];
    const float* w4r = (const float*)d_in[13];
    const float* w4i = (const float*)d_in[14];
    const float* g4  = (const float*)d_in[15];
    const float* b4  = (const float*)d_in[16];
    const float* wc  = (const float*)d_in[17];
    const float* bc  = (const float*)d_in[18];
    const float* wg  = (const float*)d_in[19];
    const float* bg  = (const float*)d_in[20];
    float* out = (float*)d_out;

    float *Y, *mean, *rstd;
    float2* part;
    __half *Xh, *Xl, *B1, *B2, *B3, *B4, *Bhd;
    cudaGetSymbolAddress((void**)&Y,   g_Y);
    cudaGetSymbolAddress((void**)&mean,g_mean);
    cudaGetSymbolAddress((void**)&rstd,g_rstd);
    cudaGetSymbolAddress((void**)&part,g_part);
    cudaGetSymbolAddress((void**)&Xh,  g_Xh);
    cudaGetSymbolAddress((void**)&Xl,  g_Xl);
    cudaGetSymbolAddress((void**)&B1,  g_B1);
    cudaGetSymbolAddress((void**)&B2,  g_B2);
    cudaGetSymbolAddress((void**)&B3,  g_B3);
    cudaGetSymbolAddress((void**)&B4,  g_B4);
    cudaGetSymbolAddress((void**)&Bhd, g_Bhd);

    // conv_dh<12>: STAGE = 18240 + 3*32*200*2 = 56640; dyn smem = 113280
    // conv_dh<9> : STAGE = 18240 + 3*32*152*2 = 47424; dyn smem =  94848
    // conv_dh<1> : STAGE = 18240 + 3*32*24*2  = 22848; dyn smem =  45696
    cudaFuncSetAttribute((const void*)conv_dh<12,true>,
                         cudaFuncAttributeMaxDynamicSharedMemorySize, 113280);
    cudaFuncSetAttribute((const void*)conv_dh<9,true>,
                         cudaFuncAttributeMaxDynamicSharedMemorySize, 94848);
    cudaFuncSetAttribute((const void*)conv_dh<1,false>,
                         cudaFuncAttributeMaxDynamicSharedMemorySize, 45696);

    // launch 0: merged weight builders; launch 1: input transpose
    const int TOTAL_B = S_B1 + S_B2 + S_B3 + S_B4 + S_BH;
    build_all<<<(TOTAL_B + 255)/256, 256>>>(w1r, w1i, w2r, w2i, w3r, w3i,
                                            w4r, w4i, wc, wg,
                                            B1, B2, B3, B4, Bhd);
    tr_in<<<dim3(PTOT/64, 8), 256>>>(x, Xh, Xl);

    // Layer 1: K=256 real, Neff=288 (2 y-blocks of 144)
    conv_dh<9,true><<<dim3(NBLK3, 2), 224, 94848>>>(Xh, Xl, B1, Y, part, 256, 288);
    bn_stats2<<<288, 256>>>(part, mean, rstd);
    bn_apply<<<(PTOT*144)/256, 256>>>(Y, 288, mean, rstd, g1, b1, Xh, Xl);

    // Layer 2: K=288, Neff=192
    conv_dh<12,true><<<dim3(NBLK3, 1), 224, 113280>>>(Xh, Xl, B2, Y, part, 288, 192);
    bn_stats2<<<192, 256>>>(part, mean, rstd);
    bn_apply<<<(PTOT*96)/256, 256>>>(Y, 192, mean, rstd, g2, b2, Xh, Xl);

    // Layer 3: K=192, Neff=192
    conv_dh<12,true><<<dim3(NBLK3, 1), 224, 113280>>>(Xh, Xl, B3, Y, part, 192, 192);
    bn_stats2<<<192, 256>>>(part, mean, rstd);
    bn_apply<<<(PTOT*96)/256, 256>>>(Y, 192, mean, rstd, g3, b3, Xh, Xl);

    // Layer 4: K=192, Neff=192, then BN+ReLU+|z| -> NHWC fp16 M (reuse Xh/Xl)
    conv_dh<12,true><<<dim3(NBLK3, 1), 224, 113280>>>(Xh, Xl, B4, Y, part, 192, 192);
    bn_stats2<<<192, 256>>>(part, mean, rstd);
    bn_mag<<<448, 96>>>(Y, mean, rstd, g4, b4, Xh, Xl);

    // head: dh-chunked conv, K=96, 16 cols (3 used) -> Y stride 16, then finish
    conv_dh<1,false><<<dim3(NBLK3, 1), 224, 45696>>>(Xh, Xl, Bhd, Y, nullptr, 96, 16);
    head_fin<<<PTOT/256, 256>>>(Y, bc, bg, out);
}

// round 16
// speedup vs baseline: 1.2863x; 1.1561x over previous
#include <cuda_runtime.h>
#include <cuda_fp16.h>
#include <mma.h>
#include <math.h>
#include <cstdint>

using namespace nvcuda;

#define HH 128
#define WW 224
#define NN 4
#define HW (HH*WW)          // 28672
#define PTOT (NN*HW)        // 114688
#define NBLK3 (PTOT/112)    // 1024 conv blocks (half image row each)

// ---------------- scratch (__device__ globals, 16B aligned) -----------------
__device__ __align__(16) float  g_Y [(size_t)PTOT*288];
__device__ __align__(16) __half g_Xh[(size_t)PTOT*288];
__device__ __align__(16) __half g_Xl[(size_t)PTOT*288];
__device__ float  g_mean[288], g_rstd[288];
__device__ __align__(16) float2 g_part[(size_t)288*NBLK3];

// weights, layout [tap][k][n], single fp16
#define S_B1 (9*256*288)
#define S_B2 (9*288*192)
#define S_B3 (9*192*192)
#define S_B4 (9*192*192)
#define S_BH (9*96*16)
__device__ __align__(16) __half g_B1[S_B1];
__device__ __align__(16) __half g_B2[S_B2];
__device__ __align__(16) __half g_B3[S_B3];
__device__ __align__(16) __half g_B4[S_B4];
__device__ __align__(16) __half g_Bhd[S_BH];

// ---------------- cp.async helpers ------------------------------------------
__device__ __forceinline__ void cp16(uint32_t s, const void* g, int sz) {
    asm volatile("cp.async.cg.shared.global [%0], [%1], 16, %2;"
                 :: "r"(s), "l"(g), "r"(sz));
}
#define CP_COMMIT() asm volatile("cp.async.commit_group;" ::: "memory")
#define CP_WAIT1()  asm volatile("cp.async.wait_group 1;" ::: "memory")

// ---------------- merged weight builder --------------------------------------
__device__ __forceinline__ float w_real(const float* wr, const float* wi,
                                        int Cin, int Neff, int idx) {
    int n = idx % Neff; int rest = idx / Neff;
    int k = rest % Cin; int tap = rest / Cin;
    int co = n >> 1, part = n & 1;
    return (part ? wi : wr)[((size_t)co*Cin + k)*9 + tap];
}
__device__ __forceinline__ float w_cplx(const float* wr, const float* wi,
                                        int Cin, int Neff, int idx) {
    int Ktot = 2*Cin;
    int n = idx % Neff; int rest = idx / Neff;
    int k2 = rest % Ktot; int tap = rest / Ktot;
    int ci = k2 >> 1, cplx = k2 & 1;
    int co = n >> 1,  part = n & 1;
    float wrv = wr[((size_t)co*Cin + ci)*9 + tap];
    float wiv = wi[((size_t)co*Cin + ci)*9 + tap];
    return (part == 0) ? (cplx == 0 ?  wrv : -wiv)
                       : (cplx == 0 ?  wiv :  wrv);
}

__global__ void build_all(const float* __restrict__ w1r, const float* __restrict__ w1i,
                          const float* __restrict__ w2r, const float* __restrict__ w2i,
                          const float* __restrict__ w3r, const float* __restrict__ w3i,
                          const float* __restrict__ w4r, const float* __restrict__ w4i,
                          const float* __restrict__ wc,  const float* __restrict__ wg,
                          __half* __restrict__ B1, __half* __restrict__ B2,
                          __half* __restrict__ B3, __half* __restrict__ B4,
                          __half* __restrict__ Bhd)
{
    int idx = blockIdx.x*256 + threadIdx.x;
    if (idx < S_B1) {
        B1[idx] = __float2half(w_real(w1r, w1i, 256, 288, idx));
        return;
    }
    idx -= S_B1;
    if (idx < S_B2) {
        B2[idx] = __float2half(w_cplx(w2r, w2i, 144, 192, idx));
        return;
    }
    idx -= S_B2;
    if (idx < S_B3) {
        B3[idx] = __float2half(w_cplx(w3r, w3i, 96, 192, idx));
        return;
    }
    idx -= S_B3;
    if (idx < S_B4) {
        B4[idx] = __float2half(w_cplx(w4r, w4i, 96, 192, idx));
        return;
    }
    idx -= S_B4;
    if (idx < S_BH) {
        int n = idx & 15; int rest = idx >> 4;
        int k = rest % 96; int tap = rest / 96;
        float v = 0.f;
        if (n == 0)      v = wc[(size_t)k*9 + tap];
        else if (n < 3)  v = wg[((size_t)(n-1)*96 + k)*9 + tap];
        Bhd[idx] = __float2half(v);
    }
}

// ---------------- input transpose: NCHW fp32 -> NHWC fp16 (K=256) -----------
// Layer 1 runs single-pass, so only the hi half is needed.
__global__ void tr_in(const float* __restrict__ x, __half* __restrict__ Xh)
{
    __shared__ float sT[32][65];
    const int t = threadIdx.x;
    const int gp = blockIdx.x * 64;
    const int cb = blockIdx.y * 32;
    const int n = gp / HW, rbas = gp % HW;
#pragma unroll
    for (int it = 0; it < 8; ++it) {
        int idx = t + it*256;
        int cc = idx >> 6, pp = idx & 63;
        sT[cc][pp] = x[((size_t)(n*256 + cb + cc))*HW + rbas + pp];
    }
    __syncthreads();
#pragma unroll
    for (int it = 0; it < 8; ++it) {
        int idx = t + it*256;
        int cc = idx & 31, pp = idx >> 5;
        Xh[(size_t)(gp + pp)*256 + cb + cc] = __float2half(sT[cc][pp]);
    }
}

// ---------------- dh-chunked tap-GEMM conv, half-row blocks ------------------
// Block = half image row: M=112 (7 warps, 224 thr), N = NFRAG*16.
// Chunk = (dh, k0): A tile (114 slots x 32 k) shared across the 3 dw taps via
// shifted wmma views; B holds 3 dw slices.
// APASS=2: D = ah*bh + al*bh (fp16 hi/lo split A). APASS=1: D = ah*bh.
template<int NFRAG, bool STATS, int APASS>
__global__ __launch_bounds__(224, 2)
void conv_dh(const __half* __restrict__ Xh,
             const __half* __restrict__ Xl,
             const __half* __restrict__ Bg,
             float* __restrict__ Y, float2* __restrict__ part,
             int K, int Neff)
{
    constexpr int NCOLS = NFRAG*16;
    constexpr int NSEG  = NCOLS/8;               // 16B segs per B row
    constexpr int BSTR  = NCOLS + 8;             // halfs
    constexpr int AHALF = 114*80;                // 9120 B (one half)
    constexpr int OBB   = 2*AHALF;               // 18240 (layout fixed)
    constexpr int STAGE = OBB + 3*32*BSTR*2;
    constexpr int ATASK = 456*APASS;
    extern __shared__ char smc[];
    const uint32_t sb = (uint32_t)__cvta_generic_to_shared(smc);

    const int t    = threadIdx.x;
    const int wid  = t >> 5;                     // 0..6
    const int tbase= blockIdx.x * 112;
    const int wb   = tbase % 224;                // 0 or 112
    const int h0   = (tbase % HW) / 224;
    const int nb   = blockIdx.y * NCOLS;
    const int kch  = K >> 5;
    const int CC   = 3 * kch;

    wmma::fragment<wmma::accumulator,16,16,16,float> acc[NFRAG];
#pragma unroll
    for (int f = 0; f < NFRAG; ++f) wmma::fill_fragment(acc[f], 0.f);

    auto LOAD = [&](int cc, int buf) {
        const uint32_t st = sb + buf*STAGE;
        int dhi = cc / kch;                      // 0..2
        int k0  = (cc - dhi*kch) << 5;
        int dh  = dhi - 1;
        bool rowok = ((unsigned)(h0 + dh) < 128u);
        // A: 114 slots x 4 segs x APASS halves
#pragma unroll
        for (int it = 0; it < (ATASK + 223)/224; ++it) {
            int task = t + it*224;
            if (task < ATASK) {
                int half = (APASS == 2) && (task >= 456);
                int t2 = half ? task - 456 : task;
                int j = t2 >> 2, seg = t2 & 3;
                int wcoord = wb + j - 1;
                bool ok = rowok && ((unsigned)wcoord < 224u);
                size_t off = ok ? ((size_t)(tbase + dh*224 + j - 1)*K + k0 + seg*8) : 0;
                cp16(st + half*AHALF + j*80 + seg*16,
                     (half ? Xl : Xh) + off, ok ? 16 : 0);
            }
        }
        // B: 3 dw x 32 rows x NSEG segs
        const int BT = 3*32*NSEG;
#pragma unroll
        for (int it = 0; it < (BT + 223)/224; ++it) {
            int task = t + it*224;
            if (task < BT) {
                int dwi = task / (32*NSEG);
                int tk  = task - dwi*(32*NSEG);
                int row = tk / NSEG, seg = tk - row*NSEG;
                int tap = dhi*3 + dwi;
                size_t off = ((size_t)tap*K + k0 + row)*Neff + nb + seg*8;
                cp16(st + OBB + dwi*(32*BSTR*2) + row*(BSTR*2) + seg*16,
                     Bg + off, 16);
            }
        }
        CP_COMMIT();
    };

    LOAD(0, 0);
    for (int cc = 0; cc < CC; ++cc) {
        const int cur = cc & 1;
        if (cc + 1 < CC) LOAD(cc+1, cur^1);
        else CP_COMMIT();                        // keep wait_group accounting
        CP_WAIT1();
        __syncthreads();
        const __half* Ah = (const __half*)(smc + cur*STAGE);
        const __half* Al = (const __half*)(smc + cur*STAGE + AHALF);
        const __half* Bb = (const __half*)(smc + cur*STAGE + OBB);
#pragma unroll
        for (int dwi = 0; dwi < 3; ++dwi) {
            const __half* Bdw = Bb + dwi*32*BSTR;
#pragma unroll
            for (int ks = 0; ks < 2; ++ks) {
                wmma::fragment<wmma::matrix_a,16,16,16,__half,wmma::row_major> ah, al;
                // output pixel row r -> A slot r + dwi
                wmma::load_matrix_sync(ah, Ah + (wid*16 + dwi)*40 + ks*16, 40);
                if (APASS == 2)
                    wmma::load_matrix_sync(al, Al + (wid*16 + dwi)*40 + ks*16, 40);
#pragma unroll
                for (int f = 0; f < NFRAG; ++f) {
                    wmma::fragment<wmma::matrix_b,16,16,16,__half,wmma::row_major> bh;
                    wmma::load_matrix_sync(bh, Bdw + ks*16*BSTR + f*16, BSTR);
                    wmma::mma_sync(acc[f], ah, bh, acc[f]);
                    if (APASS == 2)
                        wmma::mma_sync(acc[f], al, bh, acc[f]);
                }
            }
        }
        __syncthreads();
    }

    // epilogue: per-fragment wave through smem; coalesced Y writes + stats
    float*  sD = (float*)smc;                    // 7 warps x 16x20 = 8960 B
    float2* sP = (float2*)(smc + 8960);          // [14 grp][16 col]
#pragma unroll
    for (int g = 0; g < NFRAG; ++g) {
        wmma::store_matrix_sync(sD + wid*320, acc[g], 20, wmma::mem_row_major);
        __syncthreads();
#pragma unroll
        for (int it = 0; it < 2; ++it) {
            int task = t + it*224;               // 112 rows x 4 segs
            int row = task >> 2, s4 = task & 3;
            float4 v = *(const float4*)(sD + (row>>4)*320 + (row&15)*20 + s4*4);
            *(float4*)(Y + (size_t)(tbase+row)*Neff + nb + g*16 + s4*4) = v;
        }
        if (STATS) {
            int col = t & 15, grp = t >> 4;      // grp 0..13
            float s = 0.f, q = 0.f;
#pragma unroll
            for (int r8 = 0; r8 < 8; ++r8) {
                int row = grp*8 + r8;
                float v = sD[(row>>4)*320 + (row&15)*20 + col];
                s += v; q = fmaf(v, v, q);
            }
            sP[grp*16 + col] = make_float2(s, q);
        }
        __syncthreads();
        if (STATS && t < 16) {
            float s = 0.f, q = 0.f;
#pragma unroll
            for (int gg = 0; gg < 14; ++gg) {
                float2 v = sP[gg*16 + t];
                s += v.x; q += v.y;
            }
            part[(size_t)(nb + g*16 + t)*NBLK3 + blockIdx.x] = make_float2(s, q);
        }
        __syncthreads();
    }
}

// ---------------- BN stats stage 2: NBLK3 partials -> mean/rstd -------------
__global__ void bn_stats2(const float2* __restrict__ part,
                          float* __restrict__ mean, float* __restrict__ rstd)
{
    const int c = blockIdx.x, t = threadIdx.x;
    double s = 0.0, q = 0.0;
    for (int i = t; i < NBLK3; i += 256) {
        float2 v = part[(size_t)c*NBLK3 + i];
        s += (double)v.x; q += (double)v.y;
    }
    __shared__ double ss[256], sq[256];
    ss[t] = s; sq[t] = q;
    __syncthreads();
    for (int o = 128; o > 0; o >>= 1) {
        if (t < o) { ss[t] += ss[t+o]; sq[t] += sq[t+o]; }
        __syncthreads();
    }
    if (t == 0) {
        double cnt = (double)PTOT;
        double m = ss[0] / cnt;
        double var = sq[0] / cnt - m*m;
        mean[c] = (float)m;
        rstd[c] = (float)(1.0 / sqrt(var + 1e-5));
    }
}

// -------- BN apply + ReLU + fp16 hi/lo split, flat grid ----------------------
__global__ void bn_apply(const float* __restrict__ Y, int C2,
                         const float* __restrict__ mean,
                         const float* __restrict__ rstd,
                         const float* __restrict__ g, const float* __restrict__ b,
                         __half* __restrict__ Xh, __half* __restrict__ Xl)
{
    int idx = blockIdx.x*256 + threadIdx.x;      // one channel-pair per thread
    int half = C2 >> 1;
    int p = idx / half, cp = idx - p*half;
    int c = cp*2;
    const float gc = g[c>>1], bc = b[c>>1];
    const float sc0 = rstd[c]*gc,   bi0 = bc - mean[c]*sc0;
    const float sc1 = rstd[c+1]*gc, bi1 = bc - mean[c+1]*sc1;
    size_t o = (size_t)p*C2 + c;
    float2 y = *(const float2*)(Y + o);
    float v0 = fmaxf(fmaf(y.x, sc0, bi0), 0.f);
    float v1 = fmaxf(fmaf(y.y, sc1, bi1), 0.f);
    __half2 h = __floats2half2_rn(v0, v1);
    *(__half2*)(Xh + o) = h;
    float2 hf = __half22float2(h);
    *(__half2*)(Xl + o) = __floats2half2_rn(v0 - hf.x, v1 - hf.y);
}

// -------- layer-4: BN + ReLU + |z| -> NHWC fp16 hi/lo M [P,96] ---------------
__global__ void bn_mag(const float* __restrict__ Y,
                       const float* __restrict__ mean,
                       const float* __restrict__ rstd,
                       const float* __restrict__ g, const float* __restrict__ b,
                       __half* __restrict__ Mh, __half* __restrict__ Ml)
{
    const int c = threadIdx.x;                   // 96
    const int pb = blockIdx.x * 256;
    const float scr = rstd[2*c]*g[c];
    const float bir = b[c] - mean[2*c]*scr;
    const float sci = rstd[2*c+1]*g[c];
    const float bii = b[c] - mean[2*c+1]*sci;
    for (int p = 0; p < 256; ++p) {
        const float* yp = Y + (size_t)(pb+p)*192 + 2*c;
        float a = fmaxf(fmaf(yp[0], scr, bir), 0.f);
        float d = fmaxf(fmaf(yp[1], sci, bii), 0.f);
        float m = sqrtf(a*a + d*d);
        __half h = __float2half(m);
        size_t o = (size_t)(pb+p)*96 + c;
        Mh[o] = h;
        Ml[o] = __float2half(m - __half2float(h));
    }
}

// -------- head finish: bias + sigmoid(ch0) + NCHW transpose ------------------
__global__ void head_fin(const float* __restrict__ Yh,
                         const float* __restrict__ bc,
                         const float* __restrict__ bg,
                         float* __restrict__ out)
{
    int p = blockIdx.x*256 + threadIdx.x;
    float y0 = Yh[(size_t)p*16 + 0] + bc[0];
    float y1 = Yh[(size_t)p*16 + 1] + bg[0];
    float y2 = Yh[(size_t)p*16 + 2] + bg[1];
    y0 = 1.f / (1.f + expf(-y0));
    int n = p / HW, hw = p - n*HW;
    out[((size_t)(n*3 + 0))*HW + hw] = y0;
    out[((size_t)(n*3 + 1))*HW + hw] = y1;
    out[((size_t)(n*3 + 2))*HW + hw] = y2;
}

// ---------------- driver -----------------------------------------------------
extern "C" void kernel_launch(void* const* d_in, const int* in_sizes, int n_in,
                              void* d_out, int out_size)
{
    (void)in_sizes; (void)n_in; (void)out_size;
    const float* x   = (const float*)d_in[0];
    const float* w1r = (const float*)d_in[1];
    const float* w1i = (const float*)d_in[2];
    const float* g1  = (const float*)d_in[3];
    const float* b1  = (const float*)d_in[4];
    const float* w2r = (const float*)d_in[5];
    const float* w2i = (const float*)d_in[6];
    const float* g2  = (const float*)d_in[7];
    const float* b2  = (const float*)d_in[8];
    const float* w3r = (const float*)d_in[9];
    const float* w3i = (const float*)d_in[10];
    const float* g3  = (const float*)d_in[11];
    const float* b3  = (const float*)d_in[12];
    const float* w4r = (const float*)d_in[13];
    const float* w4i = (const float*)d_in[14];
    const float* g4  = (const float*)d_in[15];
    const float* b4  = (const float*)d_in[16];
    const float* wc  = (const float*)d_in[17];
    const float* bc  = (const float*)d_in[18];
    const float* wg  = (const float*)d_in[19];
    const float* bg  = (const float*)d_in[20];
    float* out = (float*)d_out;

    float *Y, *mean, *rstd;
    float2* part;
    __half *Xh, *Xl, *B1, *B2, *B3, *B4, *Bhd;
    cudaGetSymbolAddress((void**)&Y,   g_Y);
    cudaGetSymbolAddress((void**)&mean,g_mean);
    cudaGetSymbolAddress((void**)&rstd,g_rstd);
    cudaGetSymbolAddress((void**)&part,g_part);
    cudaGetSymbolAddress((void**)&Xh,  g_Xh);
    cudaGetSymbolAddress((void**)&Xl,  g_Xl);
    cudaGetSymbolAddress((void**)&B1,  g_B1);
    cudaGetSymbolAddress((void**)&B2,  g_B2);
    cudaGetSymbolAddress((void**)&B3,  g_B3);
    cudaGetSymbolAddress((void**)&B4,  g_B4);
    cudaGetSymbolAddress((void**)&Bhd, g_Bhd);

    // conv_dh<12>: STAGE = 18240 + 3*32*200*2 = 56640; dyn smem = 113280
    // conv_dh<9> : STAGE = 18240 + 3*32*152*2 = 47424; dyn smem =  94848
    // conv_dh<1> : STAGE = 18240 + 3*32*24*2  = 22848; dyn smem =  45696
    cudaFuncSetAttribute((const void*)conv_dh<12,true,2>,
                         cudaFuncAttributeMaxDynamicSharedMemorySize, 113280);
    cudaFuncSetAttribute((const void*)conv_dh<9,true,1>,
                         cudaFuncAttributeMaxDynamicSharedMemorySize, 94848);
    cudaFuncSetAttribute((const void*)conv_dh<1,false,2>,
                         cudaFuncAttributeMaxDynamicSharedMemorySize, 45696);

    const int TOTAL_B = S_B1 + S_B2 + S_B3 + S_B4 + S_BH;
    build_all<<<(TOTAL_B + 255)/256, 256>>>(w1r, w1i, w2r, w2i, w3r, w3i,
                                            w4r, w4i, wc, wg,
                                            B1, B2, B3, B4, Bhd);
    tr_in<<<dim3(PTOT/64, 8), 256>>>(x, Xh);

    // Layer 1: K=256 real, Neff=288 (2 y-blocks of 144), SINGLE-pass fp16
    conv_dh<9,true,1><<<dim3(NBLK3, 2), 224, 94848>>>(Xh, Xl, B1, Y, part, 256, 288);
    bn_stats2<<<288, 256>>>(part, mean, rstd);
    bn_apply<<<(PTOT*144)/256, 256>>>(Y, 288, mean, rstd, g1, b1, Xh, Xl);

    // Layer 2: K=288, Neff=192 (2-pass)
    conv_dh<12,true,2><<<dim3(NBLK3, 1), 224, 113280>>>(Xh, Xl, B2, Y, part, 288, 192);
    bn_stats2<<<192, 256>>>(part, mean, rstd);
    bn_apply<<<(PTOT*96)/256, 256>>>(Y, 192, mean, rstd, g2, b2, Xh, Xl);

    // Layer 3: K=192, Neff=192 (2-pass)
    conv_dh<12,true,2><<<dim3(NBLK3, 1), 224, 113280>>>(Xh, Xl, B3, Y, part, 192, 192);
    bn_stats2<<<192, 256>>>(part, mean, rstd);
    bn_apply<<<(PTOT*96)/256, 256>>>(Y, 192, mean, rstd, g3, b3, Xh, Xl);

    // Layer 4: K=192, Neff=192 (2-pass), then BN+ReLU+|z| -> NHWC fp16 M
    conv_dh<12,true,2><<<dim3(NBLK3, 1), 224, 113280>>>(Xh, Xl, B4, Y, part, 192, 192);
    bn_stats2<<<192, 256>>>(part, mean, rstd);
    bn_mag<<<448, 96>>>(Y, mean, rstd, g4, b4, Xh, Xl);

    // head: dh-chunked conv (2-pass), K=96, 16 cols (3 used), then finish
    conv_dh<1,false,2><<<dim3(NBLK3, 1), 224, 45696>>>(Xh, Xl, Bhd, Y, nullptr, 96, 16);
    head_fin<<<PTOT/256, 256>>>(Y, bc, bg, out);
}

// round 17
// speedup vs baseline: 1.4356x; 1.1161x over previous
#include <cuda_runtime.h>
#include <cuda_fp16.h>
#include <mma.h>
#include <math.h>
#include <cstdint>

using namespace nvcuda;

#define HH 128
#define WW 224
#define NN 4
#define HW (HH*WW)          // 28672
#define PTOT (NN*HW)        // 114688
#define NBLK3 (PTOT/112)    // 1024 conv blocks (half image row each)

// ---------------- scratch (__device__ globals, 16B aligned) -----------------
__device__ __align__(16) float  g_Y [(size_t)PTOT*288];
__device__ __align__(16) __half g_Xh[(size_t)PTOT*288];
__device__ __align__(16) __half g_Xl[(size_t)PTOT*288];
__device__ float  g_mean[288], g_rstd[288];
__device__ __align__(16) float2 g_part[(size_t)288*NBLK3];

// weights, layout [tap][k][n], single fp16
#define S_B1 (9*256*288)
#define S_B2 (9*288*192)
#define S_B3 (9*192*192)
#define S_B4 (9*192*192)
#define S_BH (9*96*16)
__device__ __align__(16) __half g_B1[S_B1];
__device__ __align__(16) __half g_B2[S_B2];
__device__ __align__(16) __half g_B3[S_B3];
__device__ __align__(16) __half g_B4[S_B4];
__device__ __align__(16) __half g_Bhd[S_BH];

// ---------------- cp.async helpers ------------------------------------------
__device__ __forceinline__ void cp16(uint32_t s, const void* g, int sz) {
    asm volatile("cp.async.cg.shared.global [%0], [%1], 16, %2;"
                 :: "r"(s), "l"(g), "r"(sz));
}
#define CP_COMMIT() asm volatile("cp.async.commit_group;" ::: "memory")
#define CP_WAIT1()  asm volatile("cp.async.wait_group 1;" ::: "memory")

// ---------------- merged weight builder --------------------------------------
__device__ __forceinline__ float w_real(const float* wr, const float* wi,
                                        int Cin, int Neff, int idx) {
    int n = idx % Neff; int rest = idx / Neff;
    int k = rest % Cin; int tap = rest / Cin;
    int co = n >> 1, part = n & 1;
    return (part ? wi : wr)[((size_t)co*Cin + k)*9 + tap];
}
__device__ __forceinline__ float w_cplx(const float* wr, const float* wi,
                                        int Cin, int Neff, int idx) {
    int Ktot = 2*Cin;
    int n = idx % Neff; int rest = idx / Neff;
    int k2 = rest % Ktot; int tap = rest / Ktot;
    int ci = k2 >> 1, cplx = k2 & 1;
    int co = n >> 1,  part = n & 1;
    float wrv = wr[((size_t)co*Cin + ci)*9 + tap];
    float wiv = wi[((size_t)co*Cin + ci)*9 + tap];
    return (part == 0) ? (cplx == 0 ?  wrv : -wiv)
                       : (cplx == 0 ?  wiv :  wrv);
}

__global__ void build_all(const float* __restrict__ w1r, const float* __restrict__ w1i,
                          const float* __restrict__ w2r, const float* __restrict__ w2i,
                          const float* __restrict__ w3r, const float* __restrict__ w3i,
                          const float* __restrict__ w4r, const float* __restrict__ w4i,
                          const float* __restrict__ wc,  const float* __restrict__ wg,
                          __half* __restrict__ B1, __half* __restrict__ B2,
                          __half* __restrict__ B3, __half* __restrict__ B4,
                          __half* __restrict__ Bhd)
{
    int idx = blockIdx.x*256 + threadIdx.x;
    if (idx < S_B1) {
        B1[idx] = __float2half(w_real(w1r, w1i, 256, 288, idx));
        return;
    }
    idx -= S_B1;
    if (idx < S_B2) {
        B2[idx] = __float2half(w_cplx(w2r, w2i, 144, 192, idx));
        return;
    }
    idx -= S_B2;
    if (idx < S_B3) {
        B3[idx] = __float2half(w_cplx(w3r, w3i, 96, 192, idx));
        return;
    }
    idx -= S_B3;
    if (idx < S_B4) {
        B4[idx] = __float2half(w_cplx(w4r, w4i, 96, 192, idx));
        return;
    }
    idx -= S_B4;
    if (idx < S_BH) {
        int n = idx & 15; int rest = idx >> 4;
        int k = rest % 96; int tap = rest / 96;
        float v = 0.f;
        if (n == 0)      v = wc[(size_t)k*9 + tap];
        else if (n < 3)  v = wg[((size_t)(n-1)*96 + k)*9 + tap];
        Bhd[idx] = __float2half(v);
    }
}

// ---------------- input transpose: NCHW fp32 -> NHWC fp16 (K=256) -----------
// Layer 1 runs single-pass, so only the hi half is needed.
__global__ void tr_in(const float* __restrict__ x, __half* __restrict__ Xh)
{
    __shared__ float sT[32][65];
    const int t = threadIdx.x;
    const int gp = blockIdx.x * 64;
    const int cb = blockIdx.y * 32;
    const int n = gp / HW, rbas = gp % HW;
#pragma unroll
    for (int it = 0; it < 8; ++it) {
        int idx = t + it*256;
        int cc = idx >> 6, pp = idx & 63;
        sT[cc][pp] = x[((size_t)(n*256 + cb + cc))*HW + rbas + pp];
    }
    __syncthreads();
#pragma unroll
    for (int it = 0; it < 8; ++it) {
        int idx = t + it*256;
        int cc = idx & 31, pp = idx >> 5;
        Xh[(size_t)(gp + pp)*256 + cb + cc] = __float2half(sT[cc][pp]);
    }
}

// ---------------- dh-chunked tap-GEMM conv, half-row blocks ------------------
// Block = half image row: M=112 (7 warps, 224 thr), N = NFRAG*16.
// Chunk = (dh, k0): A tile (114 slots x 32 k) shared across the 3 dw taps via
// shifted wmma views; B holds 3 dw slices.
// APASS=2: D = ah*bh + al*bh (fp16 hi/lo split A). APASS=1: D = ah*bh.
template<int NFRAG, bool STATS, int APASS>
__global__ __launch_bounds__(224, 2)
void conv_dh(const __half* __restrict__ Xh,
             const __half* __restrict__ Xl,
             const __half* __restrict__ Bg,
             float* __restrict__ Y, float2* __restrict__ part,
             int K, int Neff)
{
    constexpr int NCOLS = NFRAG*16;
    constexpr int NSEG  = NCOLS/8;               // 16B segs per B row
    constexpr int BSTR  = NCOLS + 8;             // halfs
    constexpr int AHALF = 114*80;                // 9120 B (one half)
    constexpr int OBB   = 2*AHALF;               // 18240 (layout fixed)
    constexpr int STAGE = OBB + 3*32*BSTR*2;
    constexpr int ATASK = 456*APASS;
    extern __shared__ char smc[];
    const uint32_t sb = (uint32_t)__cvta_generic_to_shared(smc);

    const int t    = threadIdx.x;
    const int wid  = t >> 5;                     // 0..6
    const int tbase= blockIdx.x * 112;
    const int wb   = tbase % 224;                // 0 or 112
    const int h0   = (tbase % HW) / 224;
    const int nb   = blockIdx.y * NCOLS;
    const int kch  = K >> 5;
    const int CC   = 3 * kch;

    wmma::fragment<wmma::accumulator,16,16,16,float> acc[NFRAG];
#pragma unroll
    for (int f = 0; f < NFRAG; ++f) wmma::fill_fragment(acc[f], 0.f);

    auto LOAD = [&](int cc, int buf) {
        const uint32_t st = sb + buf*STAGE;
        int dhi = cc / kch;                      // 0..2
        int k0  = (cc - dhi*kch) << 5;
        int dh  = dhi - 1;
        bool rowok = ((unsigned)(h0 + dh) < 128u);
        // A: 114 slots x 4 segs x APASS halves
#pragma unroll
        for (int it = 0; it < (ATASK + 223)/224; ++it) {
            int task = t + it*224;
            if (task < ATASK) {
                int half = (APASS == 2) && (task >= 456);
                int t2 = half ? task - 456 : task;
                int j = t2 >> 2, seg = t2 & 3;
                int wcoord = wb + j - 1;
                bool ok = rowok && ((unsigned)wcoord < 224u);
                size_t off = ok ? ((size_t)(tbase + dh*224 + j - 1)*K + k0 + seg*8) : 0;
                cp16(st + half*AHALF + j*80 + seg*16,
                     (half ? Xl : Xh) + off, ok ? 16 : 0);
            }
        }
        // B: 3 dw x 32 rows x NSEG segs
        const int BT = 3*32*NSEG;
#pragma unroll
        for (int it = 0; it < (BT + 223)/224; ++it) {
            int task = t + it*224;
            if (task < BT) {
                int dwi = task / (32*NSEG);
                int tk  = task - dwi*(32*NSEG);
                int row = tk / NSEG, seg = tk - row*NSEG;
                int tap = dhi*3 + dwi;
                size_t off = ((size_t)tap*K + k0 + row)*Neff + nb + seg*8;
                cp16(st + OBB + dwi*(32*BSTR*2) + row*(BSTR*2) + seg*16,
                     Bg + off, 16);
            }
        }
        CP_COMMIT();
    };

    LOAD(0, 0);
    for (int cc = 0; cc < CC; ++cc) {
        const int cur = cc & 1;
        if (cc + 1 < CC) LOAD(cc+1, cur^1);
        else CP_COMMIT();                        // keep wait_group accounting
        CP_WAIT1();
        __syncthreads();
        const __half* Ah = (const __half*)(smc + cur*STAGE);
        const __half* Al = (const __half*)(smc + cur*STAGE + AHALF);
        const __half* Bb = (const __half*)(smc + cur*STAGE + OBB);
#pragma unroll
        for (int dwi = 0; dwi < 3; ++dwi) {
            const __half* Bdw = Bb + dwi*32*BSTR;
#pragma unroll
            for (int ks = 0; ks < 2; ++ks) {
                wmma::fragment<wmma::matrix_a,16,16,16,__half,wmma::row_major> ah, al;
                // output pixel row r -> A slot r + dwi
                wmma::load_matrix_sync(ah, Ah + (wid*16 + dwi)*40 + ks*16, 40);
                if (APASS == 2)
                    wmma::load_matrix_sync(al, Al + (wid*16 + dwi)*40 + ks*16, 40);
#pragma unroll
                for (int f = 0; f < NFRAG; ++f) {
                    wmma::fragment<wmma::matrix_b,16,16,16,__half,wmma::row_major> bh;
                    wmma::load_matrix_sync(bh, Bdw + ks*16*BSTR + f*16, BSTR);
                    wmma::mma_sync(acc[f], ah, bh, acc[f]);
                    if (APASS == 2)
                        wmma::mma_sync(acc[f], al, bh, acc[f]);
                }
            }
        }
        __syncthreads();
    }

    // epilogue: per-fragment wave through smem; coalesced Y writes + stats
    float*  sD = (float*)smc;                    // 7 warps x 16x20 = 8960 B
    float2* sP = (float2*)(smc + 8960);          // [14 grp][16 col]
#pragma unroll
    for (int g = 0; g < NFRAG; ++g) {
        wmma::store_matrix_sync(sD + wid*320, acc[g], 20, wmma::mem_row_major);
        __syncthreads();
#pragma unroll
        for (int it = 0; it < 2; ++it) {
            int task = t + it*224;               // 112 rows x 4 segs
            int row = task >> 2, s4 = task & 3;
            float4 v = *(const float4*)(sD + (row>>4)*320 + (row&15)*20 + s4*4);
            *(float4*)(Y + (size_t)(tbase+row)*Neff + nb + g*16 + s4*4) = v;
        }
        if (STATS) {
            int col = t & 15, grp = t >> 4;      // grp 0..13
            float s = 0.f, q = 0.f;
#pragma unroll
            for (int r8 = 0; r8 < 8; ++r8) {
                int row = grp*8 + r8;
                float v = sD[(row>>4)*320 + (row&15)*20 + col];
                s += v; q = fmaf(v, v, q);
            }
            sP[grp*16 + col] = make_float2(s, q);
        }
        __syncthreads();
        if (STATS && t < 16) {
            float s = 0.f, q = 0.f;
#pragma unroll
            for (int gg = 0; gg < 14; ++gg) {
                float2 v = sP[gg*16 + t];
                s += v.x; q += v.y;
            }
            part[(size_t)(nb + g*16 + t)*NBLK3 + blockIdx.x] = make_float2(s, q);
        }
        __syncthreads();
    }
}

// ---------------- BN stats stage 2: NBLK3 partials -> mean/rstd -------------
__global__ void bn_stats2(const float2* __restrict__ part,
                          float* __restrict__ mean, float* __restrict__ rstd)
{
    const int c = blockIdx.x, t = threadIdx.x;
    double s = 0.0, q = 0.0;
    for (int i = t; i < NBLK3; i += 256) {
        float2 v = part[(size_t)c*NBLK3 + i];
        s += (double)v.x; q += (double)v.y;
    }
    __shared__ double ss[256], sq[256];
    ss[t] = s; sq[t] = q;
    __syncthreads();
    for (int o = 128; o > 0; o >>= 1) {
        if (t < o) { ss[t] += ss[t+o]; sq[t] += sq[t+o]; }
        __syncthreads();
    }
    if (t == 0) {
        double cnt = (double)PTOT;
        double m = ss[0] / cnt;
        double var = sq[0] / cnt - m*m;
        mean[c] = (float)m;
        rstd[c] = (float)(1.0 / sqrt(var + 1e-5));
    }
}

// -------- BN apply + ReLU + fp16 (optional lo split), flat grid --------------
__global__ void bn_apply(const float* __restrict__ Y, int C2,
                         const float* __restrict__ mean,
                         const float* __restrict__ rstd,
                         const float* __restrict__ g, const float* __restrict__ b,
                         __half* __restrict__ Xh, __half* __restrict__ Xl)
{
    int idx = blockIdx.x*256 + threadIdx.x;      // one channel-pair per thread
    int half = C2 >> 1;
    int p = idx / half, cp = idx - p*half;
    int c = cp*2;
    const float gc = g[c>>1], bc = b[c>>1];
    const float sc0 = rstd[c]*gc,   bi0 = bc - mean[c]*sc0;
    const float sc1 = rstd[c+1]*gc, bi1 = bc - mean[c+1]*sc1;
    size_t o = (size_t)p*C2 + c;
    float2 y = *(const float2*)(Y + o);
    float v0 = fmaxf(fmaf(y.x, sc0, bi0), 0.f);
    float v1 = fmaxf(fmaf(y.y, sc1, bi1), 0.f);
    __half2 h = __floats2half2_rn(v0, v1);
    *(__half2*)(Xh + o) = h;
    if (Xl) {
        float2 hf = __half22float2(h);
        *(__half2*)(Xl + o) = __floats2half2_rn(v0 - hf.x, v1 - hf.y);
    }
}

// -------- layer-4: BN + ReLU + |z| -> NHWC fp16 hi/lo M [P,96] ---------------
__global__ void bn_mag(const float* __restrict__ Y,
                       const float* __restrict__ mean,
                       const float* __restrict__ rstd,
                       const float* __restrict__ g, const float* __restrict__ b,
                       __half* __restrict__ Mh, __half* __restrict__ Ml)
{
    const int c = threadIdx.x;                   // 96
    const int pb = blockIdx.x * 256;
    const float scr = rstd[2*c]*g[c];
    const float bir = b[c] - mean[2*c]*scr;
    const float sci = rstd[2*c+1]*g[c];
    const float bii = b[c] - mean[2*c+1]*sci;
    for (int p = 0; p < 256; ++p) {
        const float* yp = Y + (size_t)(pb+p)*192 + 2*c;
        float a = fmaxf(fmaf(yp[0], scr, bir), 0.f);
        float d = fmaxf(fmaf(yp[1], sci, bii), 0.f);
        float m = sqrtf(a*a + d*d);
        __half h = __float2half(m);
        size_t o = (size_t)(pb+p)*96 + c;
        Mh[o] = h;
        Ml[o] = __float2half(m - __half2float(h));
    }
}

// -------- head finish: bias + sigmoid(ch0) + NCHW transpose ------------------
__global__ void head_fin(const float* __restrict__ Yh,
                         const float* __restrict__ bc,
                         const float* __restrict__ bg,
                         float* __restrict__ out)
{
    int p = blockIdx.x*256 + threadIdx.x;
    float y0 = Yh[(size_t)p*16 + 0] + bc[0];
    float y1 = Yh[(size_t)p*16 + 1] + bg[0];
    float y2 = Yh[(size_t)p*16 + 2] + bg[1];
    y0 = 1.f / (1.f + expf(-y0));
    int n = p / HW, hw = p - n*HW;
    out[((size_t)(n*3 + 0))*HW + hw] = y0;
    out[((size_t)(n*3 + 1))*HW + hw] = y1;
    out[((size_t)(n*3 + 2))*HW + hw] = y2;
}

// ---------------- driver -----------------------------------------------------
extern "C" void kernel_launch(void* const* d_in, const int* in_sizes, int n_in,
                              void* d_out, int out_size)
{
    (void)in_sizes; (void)n_in; (void)out_size;
    const float* x   = (const float*)d_in[0];
    const float* w1r = (const float*)d_in[1];
    const float* w1i = (const float*)d_in[2];
    const float* g1  = (const float*)d_in[3];
    const float* b1  = (const float*)d_in[4];
    const float* w2r = (const float*)d_in[5];
    const float* w2i = (const float*)d_in[6];
    const float* g2  = (const float*)d_in[7];
    const float* b2  = (const float*)d_in[8];
    const float* w3r = (const float*)d_in[9];
    const float* w3i = (const float*)d_in[10];
    const float* g3  = (const float*)d_in[11];
    const float* b3  = (const float*)d_in[12];
    const float* w4r = (const float*)d_in[13];
    const float* w4i = (const float*)d_in[14];
    const float* g4  = (const float*)d_in[15];
    const float* b4  = (const float*)d_in[16];
    const float* wc  = (const float*)d_in[17];
    const float* bc  = (const float*)d_in[18];
    const float* wg  = (const float*)d_in[19];
    const float* bg  = (const float*)d_in[20];
    float* out = (float*)d_out;

    float *Y, *mean, *rstd;
    float2* part;
    __half *Xh, *Xl, *B1, *B2, *B3, *B4, *Bhd;
    cudaGetSymbolAddress((void**)&Y,   g_Y);
    cudaGetSymbolAddress((void**)&mean,g_mean);
    cudaGetSymbolAddress((void**)&rstd,g_rstd);
    cudaGetSymbolAddress((void**)&part,g_part);
    cudaGetSymbolAddress((void**)&Xh,  g_Xh);
    cudaGetSymbolAddress((void**)&Xl,  g_Xl);
    cudaGetSymbolAddress((void**)&B1,  g_B1);
    cudaGetSymbolAddress((void**)&B2,  g_B2);
    cudaGetSymbolAddress((void**)&B3,  g_B3);
    cudaGetSymbolAddress((void**)&B4,  g_B4);
    cudaGetSymbolAddress((void**)&Bhd, g_Bhd);

    // conv_dh<12>: STAGE = 18240 + 3*32*200*2 = 56640; dyn smem = 113280
    // conv_dh<9> : STAGE = 18240 + 3*32*152*2 = 47424; dyn smem =  94848
    // conv_dh<1> : STAGE = 18240 + 3*32*24*2  = 22848; dyn smem =  45696
    cudaFuncSetAttribute((const void*)conv_dh<12,true,2>,
                         cudaFuncAttributeMaxDynamicSharedMemorySize, 113280);
    cudaFuncSetAttribute((const void*)conv_dh<12,true,1>,
                         cudaFuncAttributeMaxDynamicSharedMemorySize, 113280);
    cudaFuncSetAttribute((const void*)conv_dh<9,true,1>,
                         cudaFuncAttributeMaxDynamicSharedMemorySize, 94848);
    cudaFuncSetAttribute((const void*)conv_dh<1,false,2>,
                         cudaFuncAttributeMaxDynamicSharedMemorySize, 45696);

    const int TOTAL_B = S_B1 + S_B2 + S_B3 + S_B4 + S_BH;
    build_all<<<(TOTAL_B + 255)/256, 256>>>(w1r, w1i, w2r, w2i, w3r, w3i,
                                            w4r, w4i, wc, wg,
                                            B1, B2, B3, B4, Bhd);
    tr_in<<<dim3(PTOT/64, 8), 256>>>(x, Xh);

    // Layer 1: K=256 real, Neff=288 (2 y-blocks of 144), 1-pass fp16
    conv_dh<9,true,1><<<dim3(NBLK3, 2), 224, 94848>>>(Xh, Xl, B1, Y, part, 256, 288);
    bn_stats2<<<288, 256>>>(part, mean, rstd);
    // L2 is 1-pass: no Xl needed
    bn_apply<<<(PTOT*144)/256, 256>>>(Y, 288, mean, rstd, g1, b1, Xh, nullptr);

    // Layer 2: K=288, Neff=192, 1-pass fp16
    conv_dh<12,true,1><<<dim3(NBLK3, 1), 224, 113280>>>(Xh, Xl, B2, Y, part, 288, 192);
    bn_stats2<<<192, 256>>>(part, mean, rstd);
    bn_apply<<<(PTOT*96)/256, 256>>>(Y, 192, mean, rstd, g2, b2, Xh, Xl);

    // Layer 3: K=192, Neff=192 (2-pass)
    conv_dh<12,true,2><<<dim3(NBLK3, 1), 224, 113280>>>(Xh, Xl, B3, Y, part, 192, 192);
    bn_stats2<<<192, 256>>>(part, mean, rstd);
    bn_apply<<<(PTOT*96)/256, 256>>>(Y, 192, mean, rstd, g3, b3, Xh, Xl);

    // Layer 4: K=192, Neff=192 (2-pass), then BN+ReLU+|z| -> NHWC fp16 M
    conv_dh<12,true,2><<<dim3(NBLK3, 1), 224, 113280>>>(Xh, Xl, B4, Y, part, 192, 192);
    bn_stats2<<<192, 256>>>(part, mean, rstd);
    bn_mag<<<448, 96>>>(Y, mean, rstd, g4, b4, Xh, Xl);

    // head: dh-chunked conv (2-pass), K=96, 16 cols (3 used), then finish
    conv_dh<1,false,2><<<dim3(NBLK3, 1), 224, 45696>>>(Xh, Xl, Bhd, Y, nullptr, 96, 16);
    head_fin<<<PTOT/256, 256>>>(Y, bc, bg, out);
}